// round 2
// baseline (speedup 1.0000x reference)
#include <cuda_runtime.h>

// ---------------- problem constants ----------------
constexpr int B_  = 4;
constexpr int C_  = 64;
constexpr int HH  = 96;
constexpr int WW  = 96;
constexpr int N_  = HH * WW;        // 9216
constexpr int M_  = N_ / 2;         // 4608 (COMPRESSION = 2)
constexpr int CI  = 32;

// ---------------- scratch (no allocs allowed) ----------------
// layouts: [b][ci][n] so both producer writes and consumer tile loads are coalesced
__device__ float g_theta[B_ * CI * N_];   // 4.7 MB
__device__ float g_phi  [B_ * CI * M_];   // 2.36 MB (max-pooled)
__device__ float g_gv   [B_ * CI * M_];   // 2.36 MB (max-pooled)

// ---------------- packed f32x2 helpers ----------------
typedef unsigned long long u64;
struct __align__(16) U2 { u64 a, b; };

__device__ __forceinline__ void fma2(u64& d, u64 x, u64 y) {
    asm("fma.rn.f32x2 %0, %1, %2, %0;" : "+l"(d) : "l"(x), "l"(y));
}
__device__ __forceinline__ void mul2(u64& d, u64 x) {
    asm("mul.rn.f32x2 %0, %0, %1;" : "+l"(d) : "l"(x));
}
__device__ __forceinline__ u64 pack2(float lo, float hi) {
    u64 r;
    asm("mov.b64 %0, {%1, %2};" : "=l"(r) : "f"(lo), "f"(hi));
    return r;
}
__device__ __forceinline__ float2 unpack2(u64 v) {
    float2 f;
    asm("mov.b64 {%0, %1}, %2;" : "=f"(f.x), "=f"(f.y) : "l"(v));
    return f;
}

// =====================================================================
// Kernel A: fused 1x1-conv projections theta/phi/g + max-pool for phi,g
// grid (N/64, B), 256 threads
// =====================================================================
__global__ __launch_bounds__(256)
void proj_kernel(const float* __restrict__ x,
                 const float* __restrict__ wt, const float* __restrict__ bt,
                 const float* __restrict__ wp, const float* __restrict__ bp,
                 const float* __restrict__ wg, const float* __restrict__ bg)
{
    __shared__ float xs[C_][64];        // 16 KB : xs[c][j]
    __shared__ float ws[3][CI][C_];     // 24 KB
    __shared__ float bs[3][CI];

    const int b   = blockIdx.y;
    const int n0  = blockIdx.x * 64;
    const int m0  = blockIdx.x * 32;
    const int tid = threadIdx.x;

    // weights -> smem
    float* wflat = &ws[0][0][0];
    for (int i = tid; i < CI * C_; i += 256) {
        wflat[i]               = wt[i];
        wflat[CI * C_ + i]     = wp[i];
        wflat[2 * CI * C_ + i] = wg[i];
    }
    if (tid < CI) { bs[0][tid] = bt[tid]; bs[1][tid] = bp[tid]; bs[2][tid] = bg[tid]; }

    // x tile -> smem (coalesced: 64 contiguous floats per channel)
    for (int idx = tid; idx < C_ * 64; idx += 256) {
        const int c = idx >> 6, j = idx & 63;
        xs[c][j] = x[((size_t)b * C_ + c) * N_ + n0 + j];
    }
    __syncthreads();

    // ---- theta: 64 rows x 32 ci ; thread: j = tid&63, ci = (tid>>6) + 4u ----
    {
        const int j   = tid & 63;
        const int cib = tid >> 6;           // 0..3
        float acc[8];
#pragma unroll
        for (int u = 0; u < 8; u++) acc[u] = bs[0][cib + 4 * u];
#pragma unroll 4
        for (int c = 0; c < C_; c++) {
            const float xv = xs[c][j];
#pragma unroll
            for (int u = 0; u < 8; u++) acc[u] += xv * ws[0][cib + 4 * u][c];
        }
        float* dst = g_theta + ((size_t)b * CI) * N_ + n0 + j;
#pragma unroll
        for (int u = 0; u < 8; u++) dst[(size_t)(cib + 4 * u) * N_] = acc[u];
    }

    // ---- phi & g with max-pool over pairs: 32 pooled rows x 32 ci ----
    {
        const int jp  = tid & 31;
        const int cib = tid >> 5;           // 0..7
#pragma unroll
        for (int p = 1; p <= 2; p++) {
            float a0[4], a1[4];
#pragma unroll
            for (int u = 0; u < 4; u++) { a0[u] = 0.f; a1[u] = 0.f; }
#pragma unroll 4
            for (int c = 0; c < C_; c++) {
                const float x0 = xs[c][2 * jp];
                const float x1 = xs[c][2 * jp + 1];
#pragma unroll
                for (int u = 0; u < 4; u++) {
                    const float w = ws[p][cib + 8 * u][c];
                    a0[u] += x0 * w;
                    a1[u] += x1 * w;
                }
            }
            float* dst = (p == 1 ? g_phi : g_gv) + ((size_t)b * CI) * M_ + m0 + jp;
#pragma unroll
            for (int u = 0; u < 4; u++) {
                const int ci = cib + 8 * u;
                dst[(size_t)ci * M_] = bs[p][ci] + fmaxf(a0[u], a1[u]);
            }
        }
    }
}

// =====================================================================
// Kernel B: flash attention (fp32, packed f32x2) + output proj + residual
// grid (N/64, B), 256 threads. Q tile 64x32, KV tiles 64x32, 72 iterations.
// =====================================================================
__global__ __launch_bounds__(256)
void attn_kernel(const float* __restrict__ x,
                 const float* __restrict__ w_out,
                 const float* __restrict__ b_out,
                 float* __restrict__ out)
{
    // strides chosen so (stride/4) is odd -> row sets distinct in 16B bank-groups
    __shared__ __align__(16) float qs[64][36];   // q tile   [row][ci]
    __shared__ __align__(16) float ks[64][36];   // k tile   [m][ci]
    __shared__ __align__(16) float vs[CI][68];   // v tile   [ci][m]   (m contiguous!)
    __shared__ __align__(16) float ps[64][68];   // P tile   [row][m]
    __shared__ float salpha[64];
    __shared__ float srow[64];

    const int b   = blockIdx.y;
    const int n0  = blockIdx.x * 64;
    const int tid = threadIdx.x;

    const float* Qg = g_theta + (size_t)b * CI * N_ + n0;
    const float* Kg = g_phi   + (size_t)b * CI * M_;
    const float* Vg = g_gv    + (size_t)b * CI * M_;

    // load Q (transpose [ci][n] -> [n][ci])
    for (int idx = tid; idx < 64 * CI; idx += 256) {
        const int ci = idx >> 6, j = idx & 63;
        qs[j][ci] = Qg[(size_t)ci * N_ + j];
    }

    // S-phase thread coords
    const int ty = tid >> 4, tx = tid & 15;
    const int r0 = ty * 4;
    const float* qrow[4];
    const float* krow[4];
#pragma unroll
    for (int i = 0; i < 4; i++) qrow[i] = qs[r0 + i];
#pragma unroll
    for (int j = 0; j < 4; j++) krow[j] = ks[tx + 16 * j];

    // O-phase thread coords: 2 rows x 4 interleaved d
    const int rp = tid >> 3, colq = tid & 7;
    const int rA = 2 * rp, rB = 2 * rp + 1;

    u64 oA[4] = {0, 0, 0, 0};
    u64 oB[4] = {0, 0, 0, 0};
    float mrow[4], lrow[4];
#pragma unroll
    for (int i = 0; i < 4; i++) { mrow[i] = -1e30f; lrow[i] = 0.f; }

    const int NT = M_ / 64;   // 72
    for (int t = 0; t < NT; t++) {
        const int m0 = t * 64;
        __syncthreads();   // previous O-phase done reading ps/vs

        // load K (transposed) and V (direct, [ci][m])
        for (int idx = tid; idx < 64 * CI; idx += 256) {
            const int ci = idx >> 6, j = idx & 63;
            ks[j][ci] = Kg[(size_t)ci * M_ + m0 + j];
            vs[ci][j] = Vg[(size_t)ci * M_ + m0 + j];
        }
        __syncthreads();

        // ---- S = Q K^T  (4x4 per thread, packed over k) ----
        u64 acc[4][4];
#pragma unroll
        for (int i = 0; i < 4; i++)
#pragma unroll
            for (int j = 0; j < 4; j++) acc[i][j] = 0ull;

#pragma unroll
        for (int k = 0; k < CI; k += 4) {
            U2 qv[4], kv[4];
#pragma unroll
            for (int i = 0; i < 4; i++) qv[i] = *reinterpret_cast<const U2*>(&qrow[i][k]);
#pragma unroll
            for (int j = 0; j < 4; j++) kv[j] = *reinterpret_cast<const U2*>(&krow[j][k]);
#pragma unroll
            for (int i = 0; i < 4; i++)
#pragma unroll
                for (int j = 0; j < 4; j++) {
                    fma2(acc[i][j], qv[i].a, kv[j].a);
                    fma2(acc[i][j], qv[i].b, kv[j].b);
                }
        }

        // ---- online softmax (per row, reduce over 16 tx lanes) ----
#pragma unroll
        for (int i = 0; i < 4; i++) {
            float s[4];
#pragma unroll
            for (int j = 0; j < 4; j++) {
                const float2 f = unpack2(acc[i][j]);
                s[j] = f.x + f.y;
            }
            float mx = fmaxf(fmaxf(s[0], s[1]), fmaxf(s[2], s[3]));
#pragma unroll
            for (int off = 8; off >= 1; off >>= 1)
                mx = fmaxf(mx, __shfl_xor_sync(0xffffffffu, mx, off, 16));
            const float mnew  = fmaxf(mrow[i], mx);
            const float alpha = __expf(mrow[i] - mnew);
            float sum = 0.f;
#pragma unroll
            for (int j = 0; j < 4; j++) {
                const float p = __expf(s[j] - mnew);
                ps[r0 + i][tx + 16 * j] = p;
                sum += p;
            }
#pragma unroll
            for (int off = 8; off >= 1; off >>= 1)
                sum += __shfl_xor_sync(0xffffffffu, sum, off, 16);
            lrow[i] = lrow[i] * alpha + sum;
            mrow[i] = mnew;
            if (tx == 0) salpha[r0 + i] = alpha;
        }
        __syncthreads();

        // ---- O update: O = alpha*O + P @ V  (packed over m) ----
        {
            const float aAf = salpha[rA], aBf = salpha[rB];
            const u64 a2A = pack2(aAf, aAf);
            const u64 a2B = pack2(aBf, aBf);
#pragma unroll
            for (int i = 0; i < 4; i++) { mul2(oA[i], a2A); mul2(oB[i], a2B); }

#pragma unroll 4
            for (int m = 0; m < 64; m += 4) {
                const U2 pA = *reinterpret_cast<const U2*>(&ps[rA][m]);
                const U2 pB = *reinterpret_cast<const U2*>(&ps[rB][m]);
#pragma unroll
                for (int i = 0; i < 4; i++) {
                    const int d = colq + 8 * i;
                    const U2 vv = *reinterpret_cast<const U2*>(&vs[d][m]);
                    fma2(oA[i], pA.a, vv.a);
                    fma2(oA[i], pA.b, vv.b);
                    fma2(oB[i], pB.a, vv.a);
                    fma2(oB[i], pB.b, vv.b);
                }
            }
        }
    }

    // ---- normalize and stage O in smem (reuse qs) ----
    if (tx == 0) {
#pragma unroll
        for (int i = 0; i < 4; i++) srow[r0 + i] = lrow[i];
    }
    __syncthreads();
    {
        const float invA = 1.f / srow[rA];
        const float invB = 1.f / srow[rB];
        float (*os)[36] = qs;
#pragma unroll
        for (int i = 0; i < 4; i++) {
            const int d = colq + 8 * i;
            const float2 fA = unpack2(oA[i]);
            const float2 fB = unpack2(oB[i]);
            os[rA][d] = (fA.x + fA.y) * invA;
            os[rB][d] = (fB.x + fB.y) * invB;
        }
    }
    // load w_out into ks region (reuse)
    {
        float* wflat = &ks[0][0];
        for (int idx = tid; idx < C_ * CI; idx += 256) wflat[idx] = w_out[idx];
    }
    __syncthreads();

    // ---- output projection + residual ----
    {
        float (*os)[36] = qs;
        float (*wo)[CI] = reinterpret_cast<float (*)[CI]>(&ks[0][0]);
        const int nl = tid & 63, c0 = tid >> 6;

        float rowv[CI];
#pragma unroll
        for (int k = 0; k < CI; k += 4) {
            const float4 v = *reinterpret_cast<const float4*>(&os[nl][k]);
            rowv[k] = v.x; rowv[k + 1] = v.y; rowv[k + 2] = v.z; rowv[k + 3] = v.w;
        }
#pragma unroll
        for (int c = c0; c < C_; c += 4) {
            float acc = b_out[c];
#pragma unroll
            for (int ci = 0; ci < CI; ci++) acc += rowv[ci] * wo[c][ci];
            const size_t gi = ((size_t)b * C_ + c) * N_ + n0 + nl;
            out[gi] = acc + x[gi];
        }
    }
}

// =====================================================================
extern "C" void kernel_launch(void* const* d_in, const int* in_sizes, int n_in,
                              void* d_out, int out_size)
{
    const float* x   = (const float*)d_in[0];
    const float* wt  = (const float*)d_in[1];
    const float* bt  = (const float*)d_in[2];
    const float* wp  = (const float*)d_in[3];
    const float* bp  = (const float*)d_in[4];
    const float* wg  = (const float*)d_in[5];
    const float* bg  = (const float*)d_in[6];
    const float* wo  = (const float*)d_in[7];
    const float* bo  = (const float*)d_in[8];
    float* out = (float*)d_out;

    dim3 grid(N_ / 64, B_);
    proj_kernel<<<grid, 256>>>(x, wt, bt, wp, bp, wg, bg);
    attn_kernel<<<grid, 256>>>(x, wo, bo, out);
}

// round 5
// speedup vs baseline: 3.0529x; 3.0529x over previous
#include <cuda_runtime.h>
#include <cuda_bf16.h>
#include <cstdint>

// ---------------- problem constants ----------------
constexpr int B_  = 4;
constexpr int C_  = 64;
constexpr int HH  = 96;
constexpr int WW  = 96;
constexpr int N_  = HH * WW;        // 9216
constexpr int M_  = N_ / 2;         // 4608
constexpr int CI  = 32;
constexpr int TKV = 128;            // kv tile
constexpr int NT  = M_ / TKV;       // 36

// ---------------- scratch ----------------
// theta/phi rows: [b][n][64] bf16, cols 0-31 = hi(ci), 32-63 = lo(ci)
__device__ __nv_bfloat16 g_theta[(size_t)B_ * N_ * 64];
__device__ __nv_bfloat16 g_phi  [(size_t)B_ * M_ * 64];
// V: [b][ci][m] bf16 hi / lo
__device__ __nv_bfloat16 g_vh[(size_t)B_ * CI * M_];
__device__ __nv_bfloat16 g_vl[(size_t)B_ * CI * M_];

// ---------------- smem map (bytes, dynamic) ----------------
// Q:   128 rows x 72 bf16 (stride 144B)           = 18432
// K:   2 bufs x (128 x 72 bf16)                   = 36864
// VH:  2 bufs x (32 x 136 bf16, stride 272B)      = 17408
// VL:  2 bufs x same                              = 17408
// RED: 128 f32 row sums                           = 512
constexpr int SM_Q   = 0;
constexpr int SM_K   = 18432;
constexpr int SM_VH  = 55296;
constexpr int SM_VL  = 72704;
constexpr int SM_RED = 90112;
constexpr int SMEM_TOTAL = 90624;
constexpr int KSTRIDE = 36;   // b32 words per K/Q row
constexpr int VSTRIDE = 68;   // b32 words per V row

// ---------------- helpers ----------------
__device__ __forceinline__ uint32_t smem_u32(const void* p) {
    uint32_t a;
    asm("{ .reg .u64 t; cvta.to.shared.u64 t, %1; cvt.u32.u64 %0, t; }" : "=r"(a) : "l"(p));
    return a;
}

#define MMA_B16(cv, a, b0v, b1v)                                                  \
    asm volatile("mma.sync.aligned.m16n8k16.row.col.f32.bf16.bf16.f32 "           \
        "{%0,%1,%2,%3}, {%4,%5,%6,%7}, {%8,%9}, {%0,%1,%2,%3};"                   \
        : "+f"((cv)[0]), "+f"((cv)[1]), "+f"((cv)[2]), "+f"((cv)[3])              \
        : "r"((a)[0]), "r"((a)[1]), "r"((a)[2]), "r"((a)[3]), "r"(b0v), "r"(b1v))

#define CP16(dst, src)                                                            \
    asm volatile("cp.async.cg.shared.global [%0], [%1], 16;" :: "r"(dst), "l"(src) : "memory")

// fast exp on FMA/ALU pipes only (no MUFU): 2^(x*log2e) via magic round + deg-5 poly
__device__ __forceinline__ float fexp(float s) {
    float y = s * 1.4426950408889634f;
    float t = y + 12582912.0f;                  // round-to-nearest into mantissa
    int   n = __float_as_int(t);                // low bits = n + bias (bias<<23 == 0 mod 2^32)
    float f = y - (t - 12582912.0f);            // f in [-0.5, 0.5]
    float p = 1.3333558146e-3f;
    p = fmaf(p, f, 9.6181291076e-3f);
    p = fmaf(p, f, 5.5504108664e-2f);
    p = fmaf(p, f, 2.4022650696e-1f);
    p = fmaf(p, f, 6.9314718056e-1f);
    p = fmaf(p, f, 1.0f);
    return __int_as_float(__float_as_int(p) + (n << 23));
}

// pack (x0,x1) -> bf16x2 hi fragment, return residuals
__device__ __forceinline__ uint32_t pkhi(float x0, float x1, float& r0, float& r1) {
    __nv_bfloat162 h = __floats2bfloat162_rn(x0, x1);
    r0 = x0 - __bfloat162float(h.x);
    r1 = x1 - __bfloat162float(h.y);
    uint32_t u; *reinterpret_cast<__nv_bfloat162*>(&u) = h;
    return u;
}
__device__ __forceinline__ uint32_t pklo(float r0, float r1) {
    __nv_bfloat162 h = __floats2bfloat162_rn(r0, r1);
    uint32_t u; *reinterpret_cast<__nv_bfloat162*>(&u) = h;
    return u;
}

// =====================================================================
// Kernel A: projections -> bf16 hi/lo scratch (+ max-pool for phi, g)
// grid (144, 4), 256 threads
// =====================================================================
__global__ __launch_bounds__(256)
void proj_kernel(const float* __restrict__ x,
                 const float* __restrict__ wt, const float* __restrict__ bt,
                 const float* __restrict__ wp, const float* __restrict__ bp,
                 const float* __restrict__ wg, const float* __restrict__ bg)
{
    __shared__ float xs[C_][64];
    __shared__ float ws[3][CI][C_];
    __shared__ float bs[3][CI];

    const int b   = blockIdx.y;
    const int n0  = blockIdx.x * 64;
    const int m0  = blockIdx.x * 32;
    const int tid = threadIdx.x;

    float* wflat = &ws[0][0][0];
    for (int i = tid; i < CI * C_; i += 256) {
        wflat[i]               = wt[i];
        wflat[CI * C_ + i]     = wp[i];
        wflat[2 * CI * C_ + i] = wg[i];
    }
    if (tid < CI) { bs[0][tid] = bt[tid]; bs[1][tid] = bp[tid]; bs[2][tid] = bg[tid]; }
    for (int idx = tid; idx < C_ * 64; idx += 256) {
        const int c = idx >> 6, j = idx & 63;
        xs[c][j] = x[((size_t)b * C_ + c) * N_ + n0 + j];
    }
    __syncthreads();

    const int j   = tid & 63;
    const int cib = tid >> 6;
    float tacc[8];
#pragma unroll
    for (int u = 0; u < 8; u++) tacc[u] = bs[0][cib + 4 * u];
#pragma unroll 4
    for (int c = 0; c < C_; c++) {
        const float xv = xs[c][j];
#pragma unroll
        for (int u = 0; u < 8; u++) tacc[u] += xv * ws[0][cib + 4 * u][c];
    }

    const int jp  = tid & 31;
    const int cjb = tid >> 5;
    float pv[4], gv[4];
    {
        float p0[4], p1[4], q0[4], q1[4];
#pragma unroll
        for (int u = 0; u < 4; u++) { p0[u] = p1[u] = q0[u] = q1[u] = 0.f; }
#pragma unroll 4
        for (int c = 0; c < C_; c++) {
            const float x0 = xs[c][2 * jp];
            const float x1 = xs[c][2 * jp + 1];
#pragma unroll
            for (int u = 0; u < 4; u++) {
                const float wpv = ws[1][cjb + 8 * u][c];
                const float wgv = ws[2][cjb + 8 * u][c];
                p0[u] += x0 * wpv;  p1[u] += x1 * wpv;
                q0[u] += x0 * wgv;  q1[u] += x1 * wgv;
            }
        }
#pragma unroll
        for (int u = 0; u < 4; u++) {
            const int ci = cjb + 8 * u;
            pv[u] = bs[1][ci] + fmaxf(p0[u], p1[u]);
            gv[u] = bs[2][ci] + fmaxf(q0[u], q1[u]);
        }
    }
    __syncthreads();

    __nv_bfloat16* sth = reinterpret_cast<__nv_bfloat16*>(wflat);
    __nv_bfloat16* sph = reinterpret_cast<__nv_bfloat16*>(wflat + CI * C_);
#pragma unroll
    for (int u = 0; u < 8; u++) {
        const int ci = cib + 4 * u;
        const float v = tacc[u];
        const __nv_bfloat16 h = __float2bfloat16(v);
        sth[j * 64 + ci]      = h;
        sth[j * 64 + 32 + ci] = __float2bfloat16(v - __bfloat162float(h));
    }
#pragma unroll
    for (int u = 0; u < 4; u++) {
        const int ci = cjb + 8 * u;
        {
            const float v = pv[u];
            const __nv_bfloat16 h = __float2bfloat16(v);
            sph[jp * 64 + ci]      = h;
            sph[jp * 64 + 32 + ci] = __float2bfloat16(v - __bfloat162float(h));
        }
        {
            const float v = gv[u];
            const __nv_bfloat16 h = __float2bfloat16(v);
            const size_t gi = ((size_t)b * CI + ci) * M_ + m0 + jp;
            g_vh[gi] = h;
            g_vl[gi] = __float2bfloat16(v - __bfloat162float(h));
        }
    }
    __syncthreads();

    for (int idx = tid; idx < 512; idx += 256) {
        const int r = idx >> 3, c = idx & 7;
        *reinterpret_cast<uint4*>(&g_theta[((size_t)b * N_ + n0 + r) * 64 + c * 8]) =
            *reinterpret_cast<const uint4*>(&sth[r * 64 + c * 8]);
    }
    for (int idx = tid; idx < 256; idx += 256) {
        const int r = idx >> 3, c = idx & 7;
        *reinterpret_cast<uint4*>(&g_phi[((size_t)b * M_ + m0 + r) * 64 + c * 8]) =
            *reinterpret_cast<const uint4*>(&sph[r * 64 + c * 8]);
    }
}

// =====================================================================
// Kernel B: mma.sync flash attention + out-proj + residual
// grid (72, 4), 512 threads (16 warps), 90.6 KB dyn smem
// warp w: rows 16*(w&7) .. +15, kv-col half = w>>3
// =====================================================================
__global__ __launch_bounds__(512, 1)
void attn_kernel(const float* __restrict__ x,
                 const float* __restrict__ w_out,
                 const float* __restrict__ b_out,
                 float* __restrict__ out)
{
    extern __shared__ char smem[];
    const uint32_t sbase = smem_u32(smem);
    const int tid  = threadIdx.x;
    const int wid  = tid >> 5;
    const int lane = tid & 31;
    const int wq   = wid & 7;
    const int ch   = wid >> 3;
    const int g    = lane >> 2;
    const int tig  = lane & 3;
    const int b    = blockIdx.y;
    const int n0   = blockIdx.x * 128;

    const __nv_bfloat16* Qg  = g_theta + ((size_t)b * N_ + n0) * 64;
    const __nv_bfloat16* Kg  = g_phi   + (size_t)b * M_ * 64;
    const __nv_bfloat16* Vhg = g_vh    + (size_t)b * CI * M_;
    const __nv_bfloat16* Vlg = g_vl    + (size_t)b * CI * M_;

    // ---- stage Q (plain loads) ----
    for (int i = tid; i < 1024; i += 512) {
        const int r = i >> 3, c = i & 7;
        *reinterpret_cast<uint4*>(smem + SM_Q + r * 144 + c * 16) =
            *reinterpret_cast<const uint4*>(Qg + (size_t)r * 64 + c * 8);
    }

    // ---- cp.async tile issue ----
    auto issue_tile = [&](int t, int buf) {
        const size_t m0 = (size_t)t * TKV;
#pragma unroll
        for (int i = 0; i < 4; i++) {
            const int id = tid + i * 512;
            if (id < 1024) {
                const int r = id >> 3, c = id & 7;
                CP16(sbase + SM_K + buf * 18432 + r * 144 + c * 16,
                     Kg + (m0 + r) * 64 + c * 8);
            } else if (id < 1536) {
                const int q = id - 1024, ci = q >> 4, c = q & 15;
                CP16(sbase + SM_VH + buf * 8704 + ci * 272 + c * 16,
                     Vhg + (size_t)ci * M_ + m0 + c * 8);
            } else {
                const int q = id - 1536, ci = q >> 4, c = q & 15;
                CP16(sbase + SM_VL + buf * 8704 + ci * 272 + c * 16,
                     Vlg + (size_t)ci * M_ + m0 + c * 8);
            }
        }
    };

    issue_tile(0, 0);
    asm volatile("cp.async.commit_group;" ::: "memory");

    uint32_t qh[2][4], ql[2][4];
    float o[4][4];
#pragma unroll
    for (int i = 0; i < 4; i++)
#pragma unroll
        for (int k = 0; k < 4; k++) o[i][k] = 0.f;
    float lA = 0.f, lB = 0.f;

    const int kbase = (64 * ch + g) * KSTRIDE + tig;
    const int vbase = g * VSTRIDE + 32 * ch + tig;
    const int qbase = (16 * wq + g) * KSTRIDE + tig;

    for (int u = 0; u < NT; u++) {
        if (u + 1 < NT) {
            issue_tile(u + 1, (u + 1) & 1);
            asm volatile("cp.async.commit_group;" ::: "memory");
            asm volatile("cp.async.wait_group 1;" ::: "memory");
        } else {
            asm volatile("cp.async.wait_group 0;" ::: "memory");
        }
        __syncthreads();

        if (u == 0) {
            const uint32_t* Qb = reinterpret_cast<const uint32_t*>(smem + SM_Q);
#pragma unroll
            for (int ks = 0; ks < 2; ks++) {
                qh[ks][0] = Qb[qbase + 8 * ks];
                qh[ks][1] = Qb[qbase + 8 * KSTRIDE + 8 * ks];
                qh[ks][2] = Qb[qbase + 8 * ks + 4];
                qh[ks][3] = Qb[qbase + 8 * KSTRIDE + 8 * ks + 4];
                ql[ks][0] = Qb[qbase + 16 + 8 * ks];
                ql[ks][1] = Qb[qbase + 8 * KSTRIDE + 16 + 8 * ks];
                ql[ks][2] = Qb[qbase + 16 + 8 * ks + 4];
                ql[ks][3] = Qb[qbase + 8 * KSTRIDE + 16 + 8 * ks + 4];
            }
        }

        const int buf = u & 1;
        const uint32_t* Kb = reinterpret_cast<const uint32_t*>(smem + SM_K + buf * 18432);
        const uint32_t* Vh = reinterpret_cast<const uint32_t*>(smem + SM_VH + buf * 8704);
        const uint32_t* Vl = reinterpret_cast<const uint32_t*>(smem + SM_VL + buf * 8704);

        // ---- S = Q K^T : 8 n-tiles x 2 k-steps x 3 splits ----
        float c[8][4];
#pragma unroll
        for (int nt = 0; nt < 8; nt++)
#pragma unroll
            for (int k = 0; k < 4; k++) c[nt][k] = 0.f;

#pragma unroll
        for (int nt = 0; nt < 8; nt++) {
            const uint32_t* kr = Kb + kbase + nt * 8 * KSTRIDE;
#pragma unroll
            for (int ks = 0; ks < 2; ks++) {
                const uint32_t bh0 = kr[8 * ks],      bh1 = kr[8 * ks + 4];
                const uint32_t bl0 = kr[16 + 8 * ks], bl1 = kr[16 + 8 * ks + 4];
                MMA_B16(c[nt], qh[ks], bh0, bh1);
                MMA_B16(c[nt], qh[ks], bl0, bl1);
                MMA_B16(c[nt], ql[ks], bh0, bh1);
            }
        }

        // ---- exp (FMA-pipe) + row-sum ----
#pragma unroll
        for (int nt = 0; nt < 8; nt++) {
            c[nt][0] = fexp(c[nt][0]);
            c[nt][1] = fexp(c[nt][1]);
            c[nt][2] = fexp(c[nt][2]);
            c[nt][3] = fexp(c[nt][3]);
            lA += c[nt][0] + c[nt][1];
            lB += c[nt][2] + c[nt][3];
        }

        // ---- O += P V : 4 k-steps x 4 n-tiles x 3 splits ----
#pragma unroll
        for (int ks = 0; ks < 4; ks++) {
            uint32_t pa[4], pb[4];
            float r0, r1;
            pa[0] = pkhi(c[2 * ks][0],     c[2 * ks][1],     r0, r1); pb[0] = pklo(r0, r1);
            pa[1] = pkhi(c[2 * ks][2],     c[2 * ks][3],     r0, r1); pb[1] = pklo(r0, r1);
            pa[2] = pkhi(c[2 * ks + 1][0], c[2 * ks + 1][1], r0, r1); pb[2] = pklo(r0, r1);
            pa[3] = pkhi(c[2 * ks + 1][2], c[2 * ks + 1][3], r0, r1); pb[3] = pklo(r0, r1);
#pragma unroll
            for (int nt = 0; nt < 4; nt++) {
                const uint32_t* vr = Vh + vbase + nt * 8 * VSTRIDE + 8 * ks;
                const uint32_t* wr = Vl + vbase + nt * 8 * VSTRIDE + 8 * ks;
                const uint32_t vh0 = vr[0], vh1 = vr[4];
                const uint32_t vl0 = wr[0], vl1 = wr[4];
                MMA_B16(o[nt], pa, vh0, vh1);
                MMA_B16(o[nt], pa, vl0, vl1);
                MMA_B16(o[nt], pb, vh0, vh1);
            }
        }
        __syncthreads();
    }

    // ---- reduce l across quad lanes (rows g / g+8) ----
    lA += __shfl_xor_sync(0xffffffffu, lA, 1);
    lA += __shfl_xor_sync(0xffffffffu, lA, 2);
    lB += __shfl_xor_sync(0xffffffffu, lB, 1);
    lB += __shfl_xor_sync(0xffffffffu, lB, 2);

    // ---- combine column halves ----
    float* ost = reinterpret_cast<float*>(smem + SM_VH);    // [128][34]
    float* ls  = reinterpret_cast<float*>(smem + SM_RED);   // [128]
    float* wo  = reinterpret_cast<float*>(smem + SM_K + 18432); // [64][32]
    float* ys  = reinterpret_cast<float*>(smem + SM_K);     // [128][33]

    if (ch == 1) {
        const int r0 = 16 * wq;
#pragma unroll
        for (int nt = 0; nt < 4; nt++) {
            const int ci = 8 * nt + 2 * tig;
            ost[(r0 + g) * 34 + ci]         = o[nt][0];
            ost[(r0 + g) * 34 + ci + 1]     = o[nt][1];
            ost[(r0 + g + 8) * 34 + ci]     = o[nt][2];
            ost[(r0 + g + 8) * 34 + ci + 1] = o[nt][3];
        }
        if (tig == 0) { ls[r0 + g] = lA; ls[r0 + g + 8] = lB; }
    }
    for (int i = tid; i < C_ * CI; i += 512) wo[i] = w_out[i];
    __syncthreads();

    if (ch == 0) {
        const int r0 = 16 * wq;
        const float iA = 1.f / (lA + ls[r0 + g]);
        const float iB = 1.f / (lB + ls[r0 + g + 8]);
#pragma unroll
        for (int nt = 0; nt < 4; nt++) {
            const int ci = 8 * nt + 2 * tig;
            ys[(r0 + g) * 33 + ci]         = (o[nt][0] + ost[(r0 + g) * 34 + ci]) * iA;
            ys[(r0 + g) * 33 + ci + 1]     = (o[nt][1] + ost[(r0 + g) * 34 + ci + 1]) * iA;
            ys[(r0 + g + 8) * 33 + ci]     = (o[nt][2] + ost[(r0 + g + 8) * 34 + ci]) * iB;
            ys[(r0 + g + 8) * 33 + ci + 1] = (o[nt][3] + ost[(r0 + g + 8) * 34 + ci + 1]) * iB;
        }
    }
    __syncthreads();

    // ---- out-proj + residual: thread = (row r, 16 channels) ----
    {
        const int r  = tid & 127;
        const int cq = tid >> 7;
        float y[CI];
#pragma unroll
        for (int i = 0; i < CI; i++) y[i] = ys[r * 33 + i];
        const float* xb = x   + (size_t)b * C_ * N_;
        float*       ob = out + (size_t)b * C_ * N_;
#pragma unroll 4
        for (int c = cq * 16; c < cq * 16 + 16; c++) {
            float acc = __ldg(&b_out[c]);
            const float* w = &wo[c * CI];
#pragma unroll
            for (int i = 0; i < CI; i++) acc += y[i] * w[i];
            const size_t gi = (size_t)c * N_ + n0 + r;
            ob[gi] = acc + xb[gi];
        }
    }
}

// =====================================================================
extern "C" void kernel_launch(void* const* d_in, const int* in_sizes, int n_in,
                              void* d_out, int out_size)
{
    const float* x  = (const float*)d_in[0];
    const float* wt = (const float*)d_in[1];
    const float* bt = (const float*)d_in[2];
    const float* wp = (const float*)d_in[3];
    const float* bp = (const float*)d_in[4];
    const float* wg = (const float*)d_in[5];
    const float* bg = (const float*)d_in[6];
    const float* wo = (const float*)d_in[7];
    const float* bo = (const float*)d_in[8];
    float* out = (float*)d_out;

    static bool attr_set = false;
    if (!attr_set) {
        cudaFuncSetAttribute(attn_kernel, cudaFuncAttributeMaxDynamicSharedMemorySize, SMEM_TOTAL);
        attr_set = true;
    }

    proj_kernel<<<dim3(N_ / 64, B_), 256>>>(x, wt, bt, wp, bp, wg, bg);
    attn_kernel<<<dim3(N_ / TKV, B_), 512, SMEM_TOTAL>>>(x, wo, bo, out);
}

// round 6
// speedup vs baseline: 3.1346x; 1.0267x over previous
#include <cuda_runtime.h>
#include <cuda_bf16.h>
#include <cstdint>

// ---------------- problem constants ----------------
constexpr int B_  = 4;
constexpr int C_  = 64;
constexpr int HH  = 96;
constexpr int WW  = 96;
constexpr int N_  = HH * WW;        // 9216
constexpr int M_  = N_ / 2;         // 4608
constexpr int CI  = 32;
constexpr int TKV = 128;            // kv tile
constexpr int NT  = M_ / TKV;       // 36

// ---------------- scratch ----------------
// theta/phi rows: [b][n][64] bf16: halfwords 0-31 = hi (word-permuted), 32-63 = lo
// theta is pre-scaled by log2(e) so softmax runs in exp2 domain.
__device__ __nv_bfloat16 g_theta[(size_t)B_ * N_ * 64];
__device__ __nv_bfloat16 g_phi  [(size_t)B_ * M_ * 64];
// V: [b][ci][m] bf16 hi / lo, m permuted within 64-element runs
__device__ __nv_bfloat16 g_vh[(size_t)B_ * CI * M_];
__device__ __nv_bfloat16 g_vl[(size_t)B_ * CI * M_];

// ---------------- smem map (bytes, dynamic) ----------------
// Q:  64 rows x 192B                       = 12288
// K:  2 bufs x (128 x 192B)                = 49152
// VH: 2 bufs x (32 x 320B)                 = 20480
// VL: 2 bufs x (32 x 320B)                 = 20480
// RED: 64 f32                              = 256
constexpr int SM_Q   = 0;
constexpr int SM_K   = 12288;
constexpr int SM_VH  = 61440;
constexpr int SM_VL  = 81920;
constexpr int SM_RED = 102400;
constexpr int SMEM_TOTAL = 102656;
constexpr int KROW = 192;   // bytes per K/Q row (stride/16 = 12 == 4 mod 8 -> conflict-free LDS.128)
constexpr int VROW = 320;   // bytes per V row  (stride/16 = 20 == 4 mod 8)

// word permutation: within a 16-word group, logical word w -> phys 4*(w%4)+(w/4)
// so that frag quads (w, w+4, w+8, w+12) are physically contiguous (one LDS.128)
__host__ __device__ __forceinline__ int permw16(int w) {
    return (w & ~15) | ((w & 3) << 2) | ((w & 15) >> 2);
}

// ---------------- helpers ----------------
__device__ __forceinline__ uint32_t smem_u32(const void* p) {
    uint32_t a;
    asm("{ .reg .u64 t; cvta.to.shared.u64 t, %1; cvt.u32.u64 %0, t; }" : "=r"(a) : "l"(p));
    return a;
}

#define MMA4(cv, a0, a1, a2, a3, b0v, b1v)                                        \
    asm volatile("mma.sync.aligned.m16n8k16.row.col.f32.bf16.bf16.f32 "           \
        "{%0,%1,%2,%3}, {%4,%5,%6,%7}, {%8,%9}, {%0,%1,%2,%3};"                   \
        : "+f"((cv)[0]), "+f"((cv)[1]), "+f"((cv)[2]), "+f"((cv)[3])              \
        : "r"(a0), "r"(a1), "r"(a2), "r"(a3), "r"(b0v), "r"(b1v))

#define CP16(dst, src)                                                            \
    asm volatile("cp.async.cg.shared.global [%0], [%1], 16;" :: "r"(dst), "l"(src) : "memory")

// exp2 on FMA/ALU pipes only (input already in log2 domain)
__device__ __forceinline__ float fexp2(float s) {
    float t = s + 12582912.0f;                  // round-to-nearest integer into mantissa
    float f = s - (t - 12582912.0f);            // f in [-0.5, 0.5]
    float p = 1.3333558146e-3f;
    p = fmaf(p, f, 9.6181291076e-3f);
    p = fmaf(p, f, 5.5504108664e-2f);
    p = fmaf(p, f, 2.4022650696e-1f);
    p = fmaf(p, f, 6.9314718056e-1f);
    p = fmaf(p, f, 1.0f);
    return __int_as_float(__float_as_int(p) + (__float_as_int(t) << 23));
}

// truncation split: hi = bits&0xffff0000 packed via PRMT, residuals out
__device__ __forceinline__ uint32_t trhi(float s0, float s1, float& r0, float& r1) {
    const uint32_t b0 = __float_as_uint(s0), b1 = __float_as_uint(s1);
    r0 = s0 - __uint_as_float(b0 & 0xffff0000u);
    r1 = s1 - __uint_as_float(b1 & 0xffff0000u);
    return __byte_perm(b0, b1, 0x7632);
}
__device__ __forceinline__ uint32_t pklo(float r0, float r1) {
    __nv_bfloat162 h = __floats2bfloat162_rn(r0, r1);
    uint32_t u; *reinterpret_cast<__nv_bfloat162*>(&u) = h;
    return u;
}

// =====================================================================
// Kernel A: projections -> bf16 hi/lo scratch (permuted layouts)
// grid (144, 4), 256 threads
// =====================================================================
__global__ __launch_bounds__(256)
void proj_kernel(const float* __restrict__ x,
                 const float* __restrict__ wt, const float* __restrict__ bt,
                 const float* __restrict__ wp, const float* __restrict__ bp,
                 const float* __restrict__ wg, const float* __restrict__ bg)
{
    __shared__ float xs[C_][64];
    __shared__ float ws[3][CI][C_];
    __shared__ float bs[3][CI];

    const int b   = blockIdx.y;
    const int n0  = blockIdx.x * 64;
    const int m0  = blockIdx.x * 32;
    const int tid = threadIdx.x;

    float* wflat = &ws[0][0][0];
    for (int i = tid; i < CI * C_; i += 256) {
        wflat[i]               = wt[i];
        wflat[CI * C_ + i]     = wp[i];
        wflat[2 * CI * C_ + i] = wg[i];
    }
    if (tid < CI) { bs[0][tid] = bt[tid]; bs[1][tid] = bp[tid]; bs[2][tid] = bg[tid]; }
    for (int idx = tid; idx < C_ * 64; idx += 256) {
        const int c = idx >> 6, j = idx & 63;
        xs[c][j] = x[((size_t)b * C_ + c) * N_ + n0 + j];
    }
    __syncthreads();

    const int j   = tid & 63;
    const int cib = tid >> 6;
    float tacc[8];
#pragma unroll
    for (int u = 0; u < 8; u++) tacc[u] = bs[0][cib + 4 * u];
#pragma unroll 4
    for (int c = 0; c < C_; c++) {
        const float xv = xs[c][j];
#pragma unroll
        for (int u = 0; u < 8; u++) tacc[u] += xv * ws[0][cib + 4 * u][c];
    }

    const int jp  = tid & 31;
    const int cjb = tid >> 5;
    float pv[4], gv[4];
    {
        float p0[4], p1[4], q0[4], q1[4];
#pragma unroll
        for (int u = 0; u < 4; u++) { p0[u] = p1[u] = q0[u] = q1[u] = 0.f; }
#pragma unroll 4
        for (int c = 0; c < C_; c++) {
            const float x0 = xs[c][2 * jp];
            const float x1 = xs[c][2 * jp + 1];
#pragma unroll
            for (int u = 0; u < 4; u++) {
                const float wpv = ws[1][cjb + 8 * u][c];
                const float wgv = ws[2][cjb + 8 * u][c];
                p0[u] += x0 * wpv;  p1[u] += x1 * wpv;
                q0[u] += x0 * wgv;  q1[u] += x1 * wgv;
            }
        }
#pragma unroll
        for (int u = 0; u < 4; u++) {
            const int ci = cjb + 8 * u;
            pv[u] = bs[1][ci] + fmaxf(p0[u], p1[u]);
            gv[u] = bs[2][ci] + fmaxf(q0[u], q1[u]);
        }
    }
    __syncthreads();

    __nv_bfloat16* sth = reinterpret_cast<__nv_bfloat16*>(wflat);
    __nv_bfloat16* sph = reinterpret_cast<__nv_bfloat16*>(wflat + CI * C_);
#pragma unroll
    for (int u = 0; u < 8; u++) {
        const int ci  = cib + 4 * u;
        const int pos = permw16(ci >> 1) * 2 + (ci & 1);
        const float v = tacc[u] * 1.4426950408889634f;     // fold log2(e) into theta
        const __nv_bfloat16 h = __float2bfloat16(v);
        sth[j * 64 + pos]      = h;
        sth[j * 64 + 32 + pos] = __float2bfloat16(v - __bfloat162float(h));
    }
#pragma unroll
    for (int u = 0; u < 4; u++) {
        const int ci  = cjb + 8 * u;
        const int pos = permw16(ci >> 1) * 2 + (ci & 1);
        {
            const float v = pv[u];
            const __nv_bfloat16 h = __float2bfloat16(v);
            sph[jp * 64 + pos]      = h;
            sph[jp * 64 + 32 + pos] = __float2bfloat16(v - __bfloat162float(h));
        }
        {
            const float v = gv[u];
            const __nv_bfloat16 h = __float2bfloat16(v);
            const int m    = m0 + jp;
            const int mloc = m & 63;
            const int mp   = (m & ~63) | (permw16(mloc >> 1) * 2 + (mloc & 1));
            const size_t gi = ((size_t)b * CI + ci) * M_ + mp;
            g_vh[gi] = h;
            g_vl[gi] = __float2bfloat16(v - __bfloat162float(h));
        }
    }
    __syncthreads();

    for (int idx = tid; idx < 512; idx += 256) {
        const int r = idx >> 3, c = idx & 7;
        *reinterpret_cast<uint4*>(&g_theta[((size_t)b * N_ + n0 + r) * 64 + c * 8]) =
            *reinterpret_cast<const uint4*>(&sth[r * 64 + c * 8]);
    }
    for (int idx = tid; idx < 256; idx += 256) {
        const int r = idx >> 3, c = idx & 7;
        *reinterpret_cast<uint4*>(&g_phi[((size_t)b * M_ + m0 + r) * 64 + c * 8]) =
            *reinterpret_cast<const uint4*>(&sph[r * 64 + c * 8]);
    }
}

// =====================================================================
// Kernel B: mma.sync flash attention + out-proj + residual
// grid (144, 4), 256 threads (8 warps), 2 CTAs/SM
// warp w: q-rows 16*(w&3).., kv-col half = w>>2
// =====================================================================
__global__ __launch_bounds__(256, 2)
void attn_kernel(const float* __restrict__ x,
                 const float* __restrict__ w_out,
                 const float* __restrict__ b_out,
                 float* __restrict__ out)
{
    extern __shared__ char smem[];
    const uint32_t sbase = smem_u32(smem);
    const int tid  = threadIdx.x;
    const int wid  = tid >> 5;
    const int lane = tid & 31;
    const int wq   = wid & 3;
    const int ch   = wid >> 2;
    const int g    = lane >> 2;
    const int tig  = lane & 3;
    const int b    = blockIdx.y;
    const int n0   = blockIdx.x * 64;

    const __nv_bfloat16* Qg  = g_theta + ((size_t)b * N_ + n0) * 64;
    const __nv_bfloat16* Kg  = g_phi   + (size_t)b * M_ * 64;
    const __nv_bfloat16* Vhg = g_vh    + (size_t)b * CI * M_;
    const __nv_bfloat16* Vlg = g_vl    + (size_t)b * CI * M_;

    // ---- stage Q (plain stores; barrier below orders) ----
    for (int i = tid; i < 512; i += 256) {
        const int r = i >> 3, c = i & 7;
        *reinterpret_cast<uint4*>(smem + SM_Q + r * KROW + c * 16) =
            *reinterpret_cast<const uint4*>(Qg + (size_t)r * 64 + c * 8);
    }

    // ---- cp.async tile issue: 2048 x 16B chunks, 8 per thread ----
    auto issue_tile = [&](int t, int buf) {
        const size_t m0 = (size_t)t * TKV;
#pragma unroll
        for (int i = 0; i < 8; i++) {
            const int id = tid + i * 256;
            if (id < 1024) {
                const int r = id >> 3, c = id & 7;
                CP16(sbase + SM_K + buf * 24576 + r * KROW + c * 16,
                     Kg + (m0 + r) * 64 + c * 8);
            } else if (id < 1536) {
                const int q = id - 1024, ci = q >> 4, c = q & 15;
                CP16(sbase + SM_VH + buf * 10240 + ci * VROW + c * 16,
                     Vhg + (size_t)ci * M_ + m0 + c * 8);
            } else {
                const int q = id - 1536, ci = q >> 4, c = q & 15;
                CP16(sbase + SM_VL + buf * 10240 + ci * VROW + c * 16,
                     Vlg + (size_t)ci * M_ + m0 + c * 8);
            }
        }
    };

    issue_tile(0, 0);
    asm volatile("cp.async.commit_group;" ::: "memory");

    uint32_t qh[2][4], ql[2][4];
    float o[4][4];
#pragma unroll
    for (int i = 0; i < 4; i++)
#pragma unroll
        for (int k = 0; k < 4; k++) o[i][k] = 0.f;
    float lA = 0.f, lB = 0.f;

    for (int u = 0; u < NT; u++) {
        if (u + 1 < NT) {
            issue_tile(u + 1, (u + 1) & 1);
            asm volatile("cp.async.commit_group;" ::: "memory");
            asm volatile("cp.async.wait_group 1;" ::: "memory");
        } else {
            asm volatile("cp.async.wait_group 0;" ::: "memory");
        }
        __syncthreads();

        if (u == 0) {
            // Q fragments (permuted layout -> LDS.128 quads)
            const char* q1 = smem + SM_Q + (16 * wq + g) * KROW + 16 * tig;
            const char* q2 = smem + SM_Q + (16 * wq + g + 8) * KROW + 16 * tig;
            const uint4 hA = *reinterpret_cast<const uint4*>(q1);
            const uint4 hB = *reinterpret_cast<const uint4*>(q2);
            const uint4 lA4 = *reinterpret_cast<const uint4*>(q1 + 64);
            const uint4 lB4 = *reinterpret_cast<const uint4*>(q2 + 64);
            qh[0][0] = hA.x; qh[0][1] = hB.x; qh[0][2] = hA.y; qh[0][3] = hB.y;
            qh[1][0] = hA.z; qh[1][1] = hB.z; qh[1][2] = hA.w; qh[1][3] = hB.w;
            ql[0][0] = lA4.x; ql[0][1] = lB4.x; ql[0][2] = lA4.y; ql[0][3] = lB4.y;
            ql[1][0] = lA4.z; ql[1][1] = lB4.z; ql[1][2] = lA4.w; ql[1][3] = lB4.w;
        }

        const int buf = u & 1;
        const char* Kb = smem + SM_K + buf * 24576 + (64 * ch + g) * KROW + 16 * tig;
        const char* Vh = smem + SM_VH + buf * 10240 + g * VROW + ch * 128 + 16 * tig;
        const char* Vl = smem + SM_VL + buf * 10240 + g * VROW + ch * 128 + 16 * tig;

        // ---- S = Q K^T : 8 n-tiles, each 2 LDS.128 + 6 HMMA ----
        float c[8][4];
#pragma unroll
        for (int nt = 0; nt < 8; nt++) {
            c[nt][0] = c[nt][1] = c[nt][2] = c[nt][3] = 0.f;
            const char* kr = Kb + nt * 8 * KROW;
            const uint4 bh = *reinterpret_cast<const uint4*>(kr);
            const uint4 bl = *reinterpret_cast<const uint4*>(kr + 64);
            MMA4(c[nt], qh[0][0], qh[0][1], qh[0][2], qh[0][3], bh.x, bh.y);
            MMA4(c[nt], qh[0][0], qh[0][1], qh[0][2], qh[0][3], bl.x, bl.y);
            MMA4(c[nt], ql[0][0], ql[0][1], ql[0][2], ql[0][3], bh.x, bh.y);
            MMA4(c[nt], qh[1][0], qh[1][1], qh[1][2], qh[1][3], bh.z, bh.w);
            MMA4(c[nt], qh[1][0], qh[1][1], qh[1][2], qh[1][3], bl.z, bl.w);
            MMA4(c[nt], ql[1][0], ql[1][1], ql[1][2], ql[1][3], bh.z, bh.w);
        }

        // ---- exp2 (FMA pipe) + row sums ----
#pragma unroll
        for (int nt = 0; nt < 8; nt++) {
            c[nt][0] = fexp2(c[nt][0]);
            c[nt][1] = fexp2(c[nt][1]);
            c[nt][2] = fexp2(c[nt][2]);
            c[nt][3] = fexp2(c[nt][3]);
            lA += c[nt][0] + c[nt][1];
            lB += c[nt][2] + c[nt][3];
        }

        // ---- O += P V : 2 ks-pairs x 4 n-tiles, LDS.128 V quads ----
#pragma unroll
        for (int p = 0; p < 2; p++) {
            float r0, r1;
            uint32_t pa0[4], pb0[4], pa1[4], pb1[4];
            pa0[0] = trhi(c[4*p][0],   c[4*p][1],   r0, r1); pb0[0] = pklo(r0, r1);
            pa0[1] = trhi(c[4*p][2],   c[4*p][3],   r0, r1); pb0[1] = pklo(r0, r1);
            pa0[2] = trhi(c[4*p+1][0], c[4*p+1][1], r0, r1); pb0[2] = pklo(r0, r1);
            pa0[3] = trhi(c[4*p+1][2], c[4*p+1][3], r0, r1); pb0[3] = pklo(r0, r1);
            pa1[0] = trhi(c[4*p+2][0], c[4*p+2][1], r0, r1); pb1[0] = pklo(r0, r1);
            pa1[1] = trhi(c[4*p+2][2], c[4*p+2][3], r0, r1); pb1[1] = pklo(r0, r1);
            pa1[2] = trhi(c[4*p+3][0], c[4*p+3][1], r0, r1); pb1[2] = pklo(r0, r1);
            pa1[3] = trhi(c[4*p+3][2], c[4*p+3][3], r0, r1); pb1[3] = pklo(r0, r1);
#pragma unroll
            for (int nt = 0; nt < 4; nt++) {
                const char* vhp = Vh + nt * 8 * VROW + p * 64;
                const char* vlp = Vl + nt * 8 * VROW + p * 64;
                const uint4 vh4 = *reinterpret_cast<const uint4*>(vhp);
                const uint4 vl4 = *reinterpret_cast<const uint4*>(vlp);
                MMA4(o[nt], pa0[0], pa0[1], pa0[2], pa0[3], vh4.x, vh4.y);
                MMA4(o[nt], pa0[0], pa0[1], pa0[2], pa0[3], vl4.x, vl4.y);
                MMA4(o[nt], pb0[0], pb0[1], pb0[2], pb0[3], vh4.x, vh4.y);
                MMA4(o[nt], pa1[0], pa1[1], pa1[2], pa1[3], vh4.z, vh4.w);
                MMA4(o[nt], pa1[0], pa1[1], pa1[2], pa1[3], vl4.z, vl4.w);
                MMA4(o[nt], pb1[0], pb1[1], pb1[2], pb1[3], vh4.z, vh4.w);
            }
        }
        __syncthreads();
    }

    // ---- reduce l across quad lanes (rows g / g+8) ----
    lA += __shfl_xor_sync(0xffffffffu, lA, 1);
    lA += __shfl_xor_sync(0xffffffffu, lA, 2);
    lB += __shfl_xor_sync(0xffffffffu, lB, 1);
    lB += __shfl_xor_sync(0xffffffffu, lB, 2);

    // ---- combine column halves ----
    float* ost = reinterpret_cast<float*>(smem + SM_VH);        // [64][34]
    float* ls  = reinterpret_cast<float*>(smem + SM_RED);       // [64]
    float* ys  = reinterpret_cast<float*>(smem + SM_K);         // [64][33]
    float* wo  = reinterpret_cast<float*>(smem + SM_K + 16384); // [64][32]

    const int r0 = 16 * wq;
    if (ch == 1) {
#pragma unroll
        for (int nt = 0; nt < 4; nt++) {
            const int ci = 8 * nt + 2 * tig;
            ost[(r0 + g) * 34 + ci]         = o[nt][0];
            ost[(r0 + g) * 34 + ci + 1]     = o[nt][1];
            ost[(r0 + g + 8) * 34 + ci]     = o[nt][2];
            ost[(r0 + g + 8) * 34 + ci + 1] = o[nt][3];
        }
        if (tig == 0) { ls[r0 + g] = lA; ls[r0 + g + 8] = lB; }
    }
    for (int i = tid; i < C_ * CI; i += 256) wo[i] = w_out[i];
    __syncthreads();

    if (ch == 0) {
        const float iA = 1.f / (lA + ls[r0 + g]);
        const float iB = 1.f / (lB + ls[r0 + g + 8]);
#pragma unroll
        for (int nt = 0; nt < 4; nt++) {
            const int ci = 8 * nt + 2 * tig;
            ys[(r0 + g) * 33 + ci]         = (o[nt][0] + ost[(r0 + g) * 34 + ci]) * iA;
            ys[(r0 + g) * 33 + ci + 1]     = (o[nt][1] + ost[(r0 + g) * 34 + ci + 1]) * iA;
            ys[(r0 + g + 8) * 33 + ci]     = (o[nt][2] + ost[(r0 + g + 8) * 34 + ci]) * iB;
            ys[(r0 + g + 8) * 33 + ci + 1] = (o[nt][3] + ost[(r0 + g + 8) * 34 + ci + 1]) * iB;
        }
    }
    __syncthreads();

    // ---- out-proj + residual: thread = (row r, 16 channels) ----
    {
        const int r  = tid & 63;
        const int cq = tid >> 6;
        float y[CI];
#pragma unroll
        for (int i = 0; i < CI; i++) y[i] = ys[r * 33 + i];
        const float* xb = x   + (size_t)b * C_ * N_;
        float*       ob = out + (size_t)b * C_ * N_;
#pragma unroll 4
        for (int c = cq * 16; c < cq * 16 + 16; c++) {
            float acc = __ldg(&b_out[c]);
            const float* w = &wo[c * CI];
#pragma unroll
            for (int i = 0; i < CI; i++) acc += y[i] * w[i];
            const size_t gi = (size_t)c * N_ + n0 + r;
            ob[gi] = acc + xb[gi];
        }
    }
}

// =====================================================================
extern "C" void kernel_launch(void* const* d_in, const int* in_sizes, int n_in,
                              void* d_out, int out_size)
{
    const float* x  = (const float*)d_in[0];
    const float* wt = (const float*)d_in[1];
    const float* bt = (const float*)d_in[2];
    const float* wp = (const float*)d_in[3];
    const float* bp = (const float*)d_in[4];
    const float* wg = (const float*)d_in[5];
    const float* bg = (const float*)d_in[6];
    const float* wo = (const float*)d_in[7];
    const float* bo = (const float*)d_in[8];
    float* out = (float*)d_out;

    static bool attr_set = false;
    if (!attr_set) {
        cudaFuncSetAttribute(attn_kernel, cudaFuncAttributeMaxDynamicSharedMemorySize, SMEM_TOTAL);
        attr_set = true;
    }

    proj_kernel<<<dim3(N_ / 64, B_), 256>>>(x, wt, bt, wp, bp, wg, bg);
    attn_kernel<<<dim3(N_ / 64, B_), 256, SMEM_TOTAL>>>(x, wo, bo, out);
}

// round 7
// speedup vs baseline: 3.9037x; 1.2454x over previous
#include <cuda_runtime.h>
#include <cuda_fp16.h>
#include <cstdint>

// ---------------- problem constants ----------------
constexpr int B_  = 4;
constexpr int C_  = 64;
constexpr int HH  = 96;
constexpr int WW  = 96;
constexpr int N_  = HH * WW;        // 9216
constexpr int M_  = N_ / 2;         // 4608
constexpr int CI  = 32;
constexpr int TKV = 128;            // kv tile
constexpr int NT  = M_ / TKV;       // 36

// ---------------- scratch ----------------
// theta/phi rows: [b][n][64] fp16: halfwords 0-31 = hi (word-permuted), 32-63 = lo
// theta is pre-scaled by log2(e) so softmax runs in exp2 domain.
__device__ __half g_theta[(size_t)B_ * N_ * 64];
__device__ __half g_phi  [(size_t)B_ * M_ * 64];
// V: [b][ci][m] fp16 (single precision level; quant err 2^-12)
__device__ __half g_v[(size_t)B_ * CI * M_];

// ---------------- smem map (bytes, dynamic) ----------------
constexpr int SM_Q   = 0;          // 64 x 192B            = 12288
constexpr int SM_K   = 12288;      // 2 x (128 x 192B)     = 49152
constexpr int SM_V   = 61440;      // 2 x (32 x 320B)      = 20480
constexpr int SM_LS  = 81920;      // 64 f32
constexpr int SM_MS  = 82176;      // 64 f32
constexpr int SMEM_TOTAL = 82432;
constexpr int KROW = 192;   // stride/16 = 12 == 4 mod 8 -> conflict-free LDS.128
constexpr int VROW = 320;   // stride/16 = 20 == 4 mod 8

// word permutation: within a 16-word group, logical word w -> phys 4*(w%4)+(w/4)
__host__ __device__ __forceinline__ int permw16(int w) {
    return (w & ~15) | ((w & 3) << 2) | ((w & 15) >> 2);
}

// ---------------- helpers ----------------
__device__ __forceinline__ uint32_t smem_u32(const void* p) {
    uint32_t a;
    asm("{ .reg .u64 t; cvta.to.shared.u64 t, %1; cvt.u32.u64 %0, t; }" : "=r"(a) : "l"(p));
    return a;
}

#define MMA4(cv, a0, a1, a2, a3, b0v, b1v)                                        \
    asm volatile("mma.sync.aligned.m16n8k16.row.col.f32.f16.f16.f32 "             \
        "{%0,%1,%2,%3}, {%4,%5,%6,%7}, {%8,%9}, {%0,%1,%2,%3};"                   \
        : "+f"((cv)[0]), "+f"((cv)[1]), "+f"((cv)[2]), "+f"((cv)[3])              \
        : "r"(a0), "r"(a1), "r"(a2), "r"(a3), "r"(b0v), "r"(b1v))

#define CP16(dst, src)                                                            \
    asm volatile("cp.async.cg.shared.global [%0], [%1], 16;" :: "r"(dst), "l"(src) : "memory")

// exp2 on FMA pipes only; scale applied with one IMAD
__device__ __forceinline__ float fexp2(float d) {
    float t = d + 12582912.0f;
    float f = d - (t - 12582912.0f);
    float p = 1.3333558146e-3f;
    p = fmaf(p, f, 9.6181291076e-3f);
    p = fmaf(p, f, 5.5504108664e-2f);
    p = fmaf(p, f, 2.4022650696e-1f);
    p = fmaf(p, f, 6.9314718056e-1f);
    p = fmaf(p, f, 1.0f);
    return __int_as_float(__float_as_int(t) * 8388608 + __float_as_int(p));
}

__device__ __forceinline__ uint32_t pkh2(float a, float b) {
    __half2 h = __floats2half2_rn(a, b);
    uint32_t u; *reinterpret_cast<__half2*>(&u) = h;
    return u;
}

// =====================================================================
// Kernel A: projections -> fp16 hi/lo scratch (permuted layouts)
// grid (144, 4), 256 threads
// =====================================================================
__global__ __launch_bounds__(256)
void proj_kernel(const float* __restrict__ x,
                 const float* __restrict__ wt, const float* __restrict__ bt,
                 const float* __restrict__ wp, const float* __restrict__ bp,
                 const float* __restrict__ wg, const float* __restrict__ bg)
{
    __shared__ float xs[C_][64];
    __shared__ float ws[3][CI][C_];
    __shared__ float bs[3][CI];

    const int b   = blockIdx.y;
    const int n0  = blockIdx.x * 64;
    const int m0  = blockIdx.x * 32;
    const int tid = threadIdx.x;

    float* wflat = &ws[0][0][0];
    for (int i = tid; i < CI * C_; i += 256) {
        wflat[i]               = wt[i];
        wflat[CI * C_ + i]     = wp[i];
        wflat[2 * CI * C_ + i] = wg[i];
    }
    if (tid < CI) { bs[0][tid] = bt[tid]; bs[1][tid] = bp[tid]; bs[2][tid] = bg[tid]; }
    for (int idx = tid; idx < C_ * 64; idx += 256) {
        const int c = idx >> 6, j = idx & 63;
        xs[c][j] = x[((size_t)b * C_ + c) * N_ + n0 + j];
    }
    __syncthreads();

    const int j   = tid & 63;
    const int cib = tid >> 6;
    float tacc[8];
#pragma unroll
    for (int u = 0; u < 8; u++) tacc[u] = bs[0][cib + 4 * u];
#pragma unroll 4
    for (int c = 0; c < C_; c++) {
        const float xv = xs[c][j];
#pragma unroll
        for (int u = 0; u < 8; u++) tacc[u] += xv * ws[0][cib + 4 * u][c];
    }

    const int jp  = tid & 31;
    const int cjb = tid >> 5;
    float pv[4], gv[4];
    {
        float p0[4], p1[4], q0[4], q1[4];
#pragma unroll
        for (int u = 0; u < 4; u++) { p0[u] = p1[u] = q0[u] = q1[u] = 0.f; }
#pragma unroll 4
        for (int c = 0; c < C_; c++) {
            const float x0 = xs[c][2 * jp];
            const float x1 = xs[c][2 * jp + 1];
#pragma unroll
            for (int u = 0; u < 4; u++) {
                const float wpv = ws[1][cjb + 8 * u][c];
                const float wgv = ws[2][cjb + 8 * u][c];
                p0[u] += x0 * wpv;  p1[u] += x1 * wpv;
                q0[u] += x0 * wgv;  q1[u] += x1 * wgv;
            }
        }
#pragma unroll
        for (int u = 0; u < 4; u++) {
            const int ci = cjb + 8 * u;
            pv[u] = bs[1][ci] + fmaxf(p0[u], p1[u]);
            gv[u] = bs[2][ci] + fmaxf(q0[u], q1[u]);
        }
    }
    __syncthreads();

    __half* sth = reinterpret_cast<__half*>(wflat);
    __half* sph = reinterpret_cast<__half*>(wflat + CI * C_);
#pragma unroll
    for (int u = 0; u < 8; u++) {
        const int ci  = cib + 4 * u;
        const int pos = permw16(ci >> 1) * 2 + (ci & 1);
        const float v = tacc[u] * 1.4426950408889634f;     // log2(e) folded in
        const __half h = __float2half_rn(v);
        sth[j * 64 + pos]      = h;
        sth[j * 64 + 32 + pos] = __float2half_rn(v - __half2float(h));
    }
#pragma unroll
    for (int u = 0; u < 4; u++) {
        const int ci  = cjb + 8 * u;
        const int pos = permw16(ci >> 1) * 2 + (ci & 1);
        {
            const float v = pv[u];
            const __half h = __float2half_rn(v);
            sph[jp * 64 + pos]      = h;
            sph[jp * 64 + 32 + pos] = __float2half_rn(v - __half2float(h));
        }
        {
            const int m    = m0 + jp;
            const int mloc = m & 63;
            const int mp   = (m & ~63) | (permw16(mloc >> 1) * 2 + (mloc & 1));
            g_v[((size_t)b * CI + ci) * M_ + mp] = __float2half_rn(gv[u]);
        }
    }
    __syncthreads();

    for (int idx = tid; idx < 512; idx += 256) {
        const int r = idx >> 3, c = idx & 7;
        *reinterpret_cast<uint4*>(&g_theta[((size_t)b * N_ + n0 + r) * 64 + c * 8]) =
            *reinterpret_cast<const uint4*>(&sth[r * 64 + c * 8]);
    }
    for (int idx = tid; idx < 256; idx += 256) {
        const int r = idx >> 3, c = idx & 7;
        *reinterpret_cast<uint4*>(&g_phi[((size_t)b * M_ + m0 + r) * 64 + c * 8]) =
            *reinterpret_cast<const uint4*>(&sph[r * 64 + c * 8]);
    }
}

// =====================================================================
// Kernel B: mma.sync fp16 flash attention (online max) + out-proj + residual
// grid (144, 4), 256 threads (8 warps), 2 CTAs/SM
// warp w: q-rows 16*(w&3).., kv-col half = w>>2
// =====================================================================
__global__ __launch_bounds__(256, 2)
void attn_kernel(const float* __restrict__ x,
                 const float* __restrict__ w_out,
                 const float* __restrict__ b_out,
                 float* __restrict__ out)
{
    extern __shared__ char smem[];
    const uint32_t sbase = smem_u32(smem);
    const int tid  = threadIdx.x;
    const int wid  = tid >> 5;
    const int lane = tid & 31;
    const int wq   = wid & 3;
    const int ch   = wid >> 2;
    const int g    = lane >> 2;
    const int tig  = lane & 3;
    const int b    = blockIdx.y;
    const int n0   = blockIdx.x * 64;

    const __half* Qg = g_theta + ((size_t)b * N_ + n0) * 64;
    const __half* Kg = g_phi   + (size_t)b * M_ * 64;
    const __half* Vg = g_v     + (size_t)b * CI * M_;

    // ---- stage Q ----
    for (int i = tid; i < 512; i += 256) {
        const int r = i >> 3, c = i & 7;
        *reinterpret_cast<uint4*>(smem + SM_Q + r * KROW + c * 16) =
            *reinterpret_cast<const uint4*>(Qg + (size_t)r * 64 + c * 8);
    }

    // ---- per-thread cp.async chunk coordinates (hoisted) ----
    const int kc = tid & 7;
    const int vc = tid & 15;
    auto issue_tile = [&](int t, int buf) {
        const __half* kb = Kg + (size_t)t * TKV * 64;
        const __half* vb = Vg + (size_t)t * TKV;
        const uint32_t kd = sbase + SM_K + buf * 24576;
        const uint32_t vd = sbase + SM_V + buf * 10240;
#pragma unroll
        for (int i = 0; i < 4; i++) {
            const int r = (tid + i * 256) >> 3;
            CP16(kd + r * KROW + kc * 16, kb + (size_t)r * 64 + kc * 8);
        }
#pragma unroll
        for (int i = 0; i < 2; i++) {
            const int ci = (tid + i * 256) >> 4;
            CP16(vd + ci * VROW + vc * 16, vb + (size_t)ci * M_ + vc * 8);
        }
    };

    issue_tile(0, 0);
    asm volatile("cp.async.commit_group;" ::: "memory");
    __syncthreads();   // Q stores visible

    // ---- Q fragments (permuted layout -> LDS.128 quads) ----
    uint32_t qh[2][4], ql[2][4];
    {
        const char* q1 = smem + SM_Q + (16 * wq + g) * KROW + 16 * tig;
        const char* q2 = smem + SM_Q + (16 * wq + g + 8) * KROW + 16 * tig;
        const uint4 hA = *reinterpret_cast<const uint4*>(q1);
        const uint4 hB = *reinterpret_cast<const uint4*>(q2);
        const uint4 lA4 = *reinterpret_cast<const uint4*>(q1 + 64);
        const uint4 lB4 = *reinterpret_cast<const uint4*>(q2 + 64);
        qh[0][0] = hA.x; qh[0][1] = hB.x; qh[0][2] = hA.y; qh[0][3] = hB.y;
        qh[1][0] = hA.z; qh[1][1] = hB.z; qh[1][2] = hA.w; qh[1][3] = hB.w;
        ql[0][0] = lA4.x; ql[0][1] = lB4.x; ql[0][2] = lA4.y; ql[0][3] = lB4.y;
        ql[1][0] = lA4.z; ql[1][1] = lB4.z; ql[1][2] = lA4.w; ql[1][3] = lB4.w;
    }

    float o[4][4];
#pragma unroll
    for (int i = 0; i < 4; i++)
#pragma unroll
        for (int k = 0; k < 4; k++) o[i][k] = 0.f;
    float lA = 0.f, lB = 0.f;
    float mA = -1e30f, mB = -1e30f;

    for (int u = 0; u < NT; u++) {
        asm volatile("cp.async.wait_group 0;" ::: "memory");
        __syncthreads();   // tile u ready; all warps done with buffer (u+1)&1

        if (u + 1 < NT) {
            issue_tile(u + 1, (u + 1) & 1);
            asm volatile("cp.async.commit_group;" ::: "memory");
        }

        const int buf = u & 1;
        const char* Kb = smem + SM_K + buf * 24576 + (64 * ch + g) * KROW + 16 * tig;
        const char* Vh = smem + SM_V + buf * 10240 + g * VROW + ch * 128 + 16 * tig;

        // ---- S = Q K^T : 8 n-tiles x (2 LDS.128 + 6 HMMA) ----
        float c[8][4];
#pragma unroll
        for (int nt = 0; nt < 8; nt++) {
            c[nt][0] = c[nt][1] = c[nt][2] = c[nt][3] = 0.f;
            const char* kr = Kb + nt * 8 * KROW;
            const uint4 bh = *reinterpret_cast<const uint4*>(kr);
            const uint4 bl = *reinterpret_cast<const uint4*>(kr + 64);
            MMA4(c[nt], qh[0][0], qh[0][1], qh[0][2], qh[0][3], bh.x, bh.y);
            MMA4(c[nt], qh[0][0], qh[0][1], qh[0][2], qh[0][3], bl.x, bl.y);
            MMA4(c[nt], ql[0][0], ql[0][1], ql[0][2], ql[0][3], bh.x, bh.y);
            MMA4(c[nt], qh[1][0], qh[1][1], qh[1][2], qh[1][3], bh.z, bh.w);
            MMA4(c[nt], qh[1][0], qh[1][1], qh[1][2], qh[1][3], bl.z, bl.w);
            MMA4(c[nt], ql[1][0], ql[1][1], ql[1][2], ql[1][3], bh.z, bh.w);
        }

        // ---- running max + O/l rescale ----
        float mxA = fmaxf(c[0][0], c[0][1]);
        float mxB = fmaxf(c[0][2], c[0][3]);
#pragma unroll
        for (int nt = 1; nt < 8; nt++) {
            mxA = fmaxf(mxA, fmaxf(c[nt][0], c[nt][1]));
            mxB = fmaxf(mxB, fmaxf(c[nt][2], c[nt][3]));
        }
        mxA = fmaxf(mxA, __shfl_xor_sync(0xffffffffu, mxA, 1));
        mxA = fmaxf(mxA, __shfl_xor_sync(0xffffffffu, mxA, 2));
        mxB = fmaxf(mxB, __shfl_xor_sync(0xffffffffu, mxB, 1));
        mxB = fmaxf(mxB, __shfl_xor_sync(0xffffffffu, mxB, 2));
        const float mAn = fmaxf(mA, mxA);
        const float mBn = fmaxf(mB, mxB);
        const float sA  = fexp2(fmaxf(mA - mAn, -126.f));
        const float sB  = fexp2(fmaxf(mB - mBn, -126.f));
        mA = mAn; mB = mBn;
        lA *= sA; lB *= sB;
#pragma unroll
        for (int nt = 0; nt < 4; nt++) {
            o[nt][0] *= sA; o[nt][1] *= sA;
            o[nt][2] *= sB; o[nt][3] *= sB;
        }

        // ---- exp2(s - m) + row sums ----
#pragma unroll
        for (int nt = 0; nt < 8; nt++) {
            c[nt][0] = fexp2(c[nt][0] - mA);
            c[nt][1] = fexp2(c[nt][1] - mA);
            c[nt][2] = fexp2(c[nt][2] - mB);
            c[nt][3] = fexp2(c[nt][3] - mB);
            lA += c[nt][0] + c[nt][1];
            lB += c[nt][2] + c[nt][3];
        }

        // ---- O += P V : fp16 single product ----
#pragma unroll
        for (int p = 0; p < 2; p++) {
            uint32_t pa0[4], pa1[4];
            pa0[0] = pkh2(c[4*p][0],   c[4*p][1]);
            pa0[1] = pkh2(c[4*p][2],   c[4*p][3]);
            pa0[2] = pkh2(c[4*p+1][0], c[4*p+1][1]);
            pa0[3] = pkh2(c[4*p+1][2], c[4*p+1][3]);
            pa1[0] = pkh2(c[4*p+2][0], c[4*p+2][1]);
            pa1[1] = pkh2(c[4*p+2][2], c[4*p+2][3]);
            pa1[2] = pkh2(c[4*p+3][0], c[4*p+3][1]);
            pa1[3] = pkh2(c[4*p+3][2], c[4*p+3][3]);
#pragma unroll
            for (int nt = 0; nt < 4; nt++) {
                const uint4 vh4 = *reinterpret_cast<const uint4*>(Vh + nt * 8 * VROW + p * 64);
                MMA4(o[nt], pa0[0], pa0[1], pa0[2], pa0[3], vh4.x, vh4.y);
                MMA4(o[nt], pa1[0], pa1[1], pa1[2], pa1[3], vh4.z, vh4.w);
            }
        }
    }

    // ---- reduce l across quad lanes (m already quad-uniform) ----
    lA += __shfl_xor_sync(0xffffffffu, lA, 1);
    lA += __shfl_xor_sync(0xffffffffu, lA, 2);
    lB += __shfl_xor_sync(0xffffffffu, lB, 1);
    lB += __shfl_xor_sync(0xffffffffu, lB, 2);

    // ---- combine column halves (max-aware) ----
    float* ost = reinterpret_cast<float*>(smem + SM_V);         // [64][34]
    float* ls  = reinterpret_cast<float*>(smem + SM_LS);        // [64]
    float* ms  = reinterpret_cast<float*>(smem + SM_MS);        // [64]
    float* ys  = reinterpret_cast<float*>(smem + SM_K);         // [64][33]
    float* wo  = reinterpret_cast<float*>(smem + SM_K + 16384); // [64][32]

    const int rA = 16 * wq + g, rB = rA + 8;
    if (ch == 1) {
#pragma unroll
        for (int nt = 0; nt < 4; nt++) {
            const int ci = 8 * nt + 2 * tig;
            ost[rA * 34 + ci]     = o[nt][0];
            ost[rA * 34 + ci + 1] = o[nt][1];
            ost[rB * 34 + ci]     = o[nt][2];
            ost[rB * 34 + ci + 1] = o[nt][3];
        }
        if (tig == 0) { ls[rA] = lA; ls[rB] = lB; ms[rA] = mA; ms[rB] = mB; }
    }
    for (int i = tid; i < C_ * CI; i += 256) wo[i] = w_out[i];
    __syncthreads();

    if (ch == 0) {
        const float m1A = ms[rA], m1B = ms[rB];
        const float MtA = fmaxf(mA, m1A), MtB = fmaxf(mB, m1B);
        const float a0 = fexp2(fmaxf(mA - MtA, -126.f));
        const float a1 = fexp2(fmaxf(m1A - MtA, -126.f));
        const float b0 = fexp2(fmaxf(mB - MtB, -126.f));
        const float b1 = fexp2(fmaxf(m1B - MtB, -126.f));
        const float iA = 1.f / (lA * a0 + ls[rA] * a1);
        const float iB = 1.f / (lB * b0 + ls[rB] * b1);
        const float fA0 = a0 * iA, fA1 = a1 * iA;
        const float fB0 = b0 * iB, fB1 = b1 * iB;
#pragma unroll
        for (int nt = 0; nt < 4; nt++) {
            const int ci = 8 * nt + 2 * tig;
            ys[rA * 33 + ci]     = o[nt][0] * fA0 + ost[rA * 34 + ci]     * fA1;
            ys[rA * 33 + ci + 1] = o[nt][1] * fA0 + ost[rA * 34 + ci + 1] * fA1;
            ys[rB * 33 + ci]     = o[nt][2] * fB0 + ost[rB * 34 + ci]     * fB1;
            ys[rB * 33 + ci + 1] = o[nt][3] * fB0 + ost[rB * 34 + ci + 1] * fB1;
        }
    }
    __syncthreads();

    // ---- out-proj + residual: thread = (row r, 16 channels) ----
    {
        const int r  = tid & 63;
        const int cq = tid >> 6;
        float y[CI];
#pragma unroll
        for (int i = 0; i < CI; i++) y[i] = ys[r * 33 + i];
        const float* xb = x   + (size_t)b * C_ * N_;
        float*       ob = out + (size_t)b * C_ * N_;
#pragma unroll 4
        for (int c = cq * 16; c < cq * 16 + 16; c++) {
            float acc = __ldg(&b_out[c]);
            const float* w = &wo[c * CI];
#pragma unroll
            for (int i = 0; i < CI; i++) acc += y[i] * w[i];
            const size_t gi = (size_t)c * N_ + n0 + r;
            ob[gi] = acc + xb[gi];
        }
    }
}

// =====================================================================
extern "C" void kernel_launch(void* const* d_in, const int* in_sizes, int n_in,
                              void* d_out, int out_size)
{
    const float* x  = (const float*)d_in[0];
    const float* wt = (const float*)d_in[1];
    const float* bt = (const float*)d_in[2];
    const float* wp = (const float*)d_in[3];
    const float* bp = (const float*)d_in[4];
    const float* wg = (const float*)d_in[5];
    const float* bg = (const float*)d_in[6];
    const float* wo = (const float*)d_in[7];
    const float* bo = (const float*)d_in[8];
    float* out = (float*)d_out;

    static bool attr_set = false;
    if (!attr_set) {
        cudaFuncSetAttribute(attn_kernel, cudaFuncAttributeMaxDynamicSharedMemorySize, SMEM_TOTAL);
        attr_set = true;
    }

    proj_kernel<<<dim3(N_ / 64, B_), 256>>>(x, wt, bt, wp, bp, wg, bg);
    attn_kernel<<<dim3(N_ / 64, B_), 256, SMEM_TOTAL>>>(x, wo, bo, out);
}

// round 9
// speedup vs baseline: 4.0078x; 1.0267x over previous
#include <cuda_runtime.h>
#include <cuda_fp16.h>
#include <cstdint>

// ---------------- problem constants ----------------
constexpr int B_  = 4;
constexpr int C_  = 64;
constexpr int HH  = 96;
constexpr int WW  = 96;
constexpr int N_  = HH * WW;        // 9216
constexpr int M_  = N_ / 2;         // 4608
constexpr int CI  = 32;
constexpr int TKV = 128;            // kv tile
constexpr int NT  = M_ / TKV;       // 36

// ---------------- scratch ----------------
// theta/phi rows: [b][n][64] fp16: halfwords 0-31 = hi (word-permuted), 32-63 = lo
// theta is pre-scaled by log2(e) so softmax runs in exp2 domain.
__device__ __half g_theta[(size_t)B_ * N_ * 64];
__device__ __half g_phi  [(size_t)B_ * M_ * 64];
// V: [b][ci][m] fp16 (single precision level; quant err 2^-12)
__device__ __half g_v[(size_t)B_ * CI * M_];

// ---------------- smem map (bytes, dynamic) ----------------
constexpr int SM_Q   = 0;          // 64 x 192B            = 12288
constexpr int SM_K   = 12288;      // 2 x (128 x 192B)     = 49152
constexpr int SM_V   = 61440;      // 2 x (32 x 320B)      = 20480
constexpr int SM_LS  = 81920;      // 64 f32
constexpr int SM_MS  = 82176;      // 64 f32
constexpr int SMEM_TOTAL = 82432;
constexpr int KROW = 192;   // stride/16 = 12 == 4 mod 8 -> conflict-free LDS.128
constexpr int VROW = 320;   // stride/16 = 20 == 4 mod 8

// word permutation: within a 16-word group, logical word w -> phys 4*(w%4)+(w/4)
__host__ __device__ __forceinline__ int permw16(int w) {
    return (w & ~15) | ((w & 3) << 2) | ((w & 15) >> 2);
}

// ---------------- helpers ----------------
__device__ __forceinline__ uint32_t smem_u32(const void* p) {
    uint32_t a;
    asm("{ .reg .u64 t; cvta.to.shared.u64 t, %1; cvt.u32.u64 %0, t; }" : "=r"(a) : "l"(p));
    return a;
}

#define MMA4(cv, a0, a1, a2, a3, b0v, b1v)                                        \
    asm volatile("mma.sync.aligned.m16n8k16.row.col.f32.f16.f16.f32 "             \
        "{%0,%1,%2,%3}, {%4,%5,%6,%7}, {%8,%9}, {%0,%1,%2,%3};"                   \
        : "+f"((cv)[0]), "+f"((cv)[1]), "+f"((cv)[2]), "+f"((cv)[3])              \
        : "r"(a0), "r"(a1), "r"(a2), "r"(a3), "r"(b0v), "r"(b1v))

#define CP16(dst, src)                                                            \
    asm volatile("cp.async.cg.shared.global [%0], [%1], 16;" :: "r"(dst), "l"(src) : "memory")

// exp2, deg-4 Taylor, FMA pipe only. Used for rescale factors whose
// arguments are exact INTEGER differences (running max is integer-quantized).
__device__ __forceinline__ float fexp2(float d) {
    float t = d + 12582912.0f;
    float f = d - (t - 12582912.0f);
    float p = 0.00961813f;
    p = fmaf(p, f, 0.05550411f);
    p = fmaf(p, f, 0.24022651f);
    p = fmaf(p, f, 0.69314718f);
    p = fmaf(p, f, 1.0f);
    return __int_as_float(__float_as_int(t) * 8388608 + __float_as_int(p));
}

// exp2(c - m) with INTEGER m folded into the magic constant K1 = 12582912 - m.
// m integer => K1 exact => computes exp2(c - m) (R8 bug: non-integer m got
// silently rounded inside K1, desyncing P from the rescale chain).
__device__ __forceinline__ float fexp2f(float c, float K1) {
    float t = c + K1;                       // 12582912 + round(c - m)
    float u = K1 - t;                       // exact (Sterbenz)
    float f = u + c;                        // (c - m) - round(c - m)
    float p = 0.00961813f;
    p = fmaf(p, f, 0.05550411f);
    p = fmaf(p, f, 0.24022651f);
    p = fmaf(p, f, 0.69314718f);
    p = fmaf(p, f, 1.0f);
    return __int_as_float(__float_as_int(t) * 8388608 + __float_as_int(p));
}

__device__ __forceinline__ uint32_t pkh2(float a, float b) {
    __half2 h = __floats2half2_rn(a, b);
    uint32_t u; *reinterpret_cast<__half2*>(&u) = h;
    return u;
}

// =====================================================================
// Kernel A: projections -> fp16 hi/lo scratch (permuted layouts)
// grid (144, 4), 256 threads
// =====================================================================
__global__ __launch_bounds__(256)
void proj_kernel(const float* __restrict__ x,
                 const float* __restrict__ wt, const float* __restrict__ bt,
                 const float* __restrict__ wp, const float* __restrict__ bp,
                 const float* __restrict__ wg, const float* __restrict__ bg)
{
    __shared__ float xs[C_][64];
    __shared__ float ws[3][CI][C_];
    __shared__ float bs[3][CI];

    const int b   = blockIdx.y;
    const int n0  = blockIdx.x * 64;
    const int m0  = blockIdx.x * 32;
    const int tid = threadIdx.x;

    float* wflat = &ws[0][0][0];
    for (int i = tid; i < CI * C_; i += 256) {
        wflat[i]               = wt[i];
        wflat[CI * C_ + i]     = wp[i];
        wflat[2 * CI * C_ + i] = wg[i];
    }
    if (tid < CI) { bs[0][tid] = bt[tid]; bs[1][tid] = bp[tid]; bs[2][tid] = bg[tid]; }
    for (int idx = tid; idx < C_ * 64; idx += 256) {
        const int c = idx >> 6, j = idx & 63;
        xs[c][j] = x[((size_t)b * C_ + c) * N_ + n0 + j];
    }
    __syncthreads();

    const int j   = tid & 63;
    const int cib = tid >> 6;
    float tacc[8];
#pragma unroll
    for (int u = 0; u < 8; u++) tacc[u] = bs[0][cib + 4 * u];
#pragma unroll 4
    for (int c = 0; c < C_; c++) {
        const float xv = xs[c][j];
#pragma unroll
        for (int u = 0; u < 8; u++) tacc[u] += xv * ws[0][cib + 4 * u][c];
    }

    const int jp  = tid & 31;
    const int cjb = tid >> 5;
    float pv[4], gv[4];
    {
        float p0[4], p1[4], q0[4], q1[4];
#pragma unroll
        for (int u = 0; u < 4; u++) { p0[u] = p1[u] = q0[u] = q1[u] = 0.f; }
#pragma unroll 4
        for (int c = 0; c < C_; c++) {
            const float x0 = xs[c][2 * jp];
            const float x1 = xs[c][2 * jp + 1];
#pragma unroll
            for (int u = 0; u < 4; u++) {
                const float wpv = ws[1][cjb + 8 * u][c];
                const float wgv = ws[2][cjb + 8 * u][c];
                p0[u] += x0 * wpv;  p1[u] += x1 * wpv;
                q0[u] += x0 * wgv;  q1[u] += x1 * wgv;
            }
        }
#pragma unroll
        for (int u = 0; u < 4; u++) {
            const int ci = cjb + 8 * u;
            pv[u] = bs[1][ci] + fmaxf(p0[u], p1[u]);
            gv[u] = bs[2][ci] + fmaxf(q0[u], q1[u]);
        }
    }
    __syncthreads();

    __half* sth = reinterpret_cast<__half*>(wflat);
    __half* sph = reinterpret_cast<__half*>(wflat + CI * C_);
#pragma unroll
    for (int u = 0; u < 8; u++) {
        const int ci  = cib + 4 * u;
        const int pos = permw16(ci >> 1) * 2 + (ci & 1);
        const float v = tacc[u] * 1.4426950408889634f;     // log2(e) folded in
        const __half h = __float2half_rn(v);
        sth[j * 64 + pos]      = h;
        sth[j * 64 + 32 + pos] = __float2half_rn(v - __half2float(h));
    }
#pragma unroll
    for (int u = 0; u < 4; u++) {
        const int ci  = cjb + 8 * u;
        const int pos = permw16(ci >> 1) * 2 + (ci & 1);
        {
            const float v = pv[u];
            const __half h = __float2half_rn(v);
            sph[jp * 64 + pos]      = h;
            sph[jp * 64 + 32 + pos] = __float2half_rn(v - __half2float(h));
        }
        {
            const int m    = m0 + jp;
            const int mloc = m & 63;
            const int mp   = (m & ~63) | (permw16(mloc >> 1) * 2 + (mloc & 1));
            g_v[((size_t)b * CI + ci) * M_ + mp] = __float2half_rn(gv[u]);
        }
    }
    __syncthreads();

    for (int idx = tid; idx < 512; idx += 256) {
        const int r = idx >> 3, c = idx & 7;
        *reinterpret_cast<uint4*>(&g_theta[((size_t)b * N_ + n0 + r) * 64 + c * 8]) =
            *reinterpret_cast<const uint4*>(&sth[r * 64 + c * 8]);
    }
    for (int idx = tid; idx < 256; idx += 256) {
        const int r = idx >> 3, c = idx & 7;
        *reinterpret_cast<uint4*>(&g_phi[((size_t)b * M_ + m0 + r) * 64 + c * 8]) =
            *reinterpret_cast<const uint4*>(&sph[r * 64 + c * 8]);
    }
}

// =====================================================================
// Kernel B: mma.sync fp16 flash attention (integer online max, MMA-computed l)
// grid (144, 4), 256 threads (8 warps), 2 CTAs/SM
// warp w: q-rows 16*(w&3).., kv-col half = w>>2
// =====================================================================
__global__ __launch_bounds__(256, 2)
void attn_kernel(const float* __restrict__ x,
                 const float* __restrict__ w_out,
                 const float* __restrict__ b_out,
                 float* __restrict__ out)
{
    extern __shared__ char smem[];
    const uint32_t sbase = smem_u32(smem);
    const int tid  = threadIdx.x;
    const int wid  = tid >> 5;
    const int lane = tid & 31;
    const int wq   = wid & 3;
    const int ch   = wid >> 2;
    const int g    = lane >> 2;
    const int tig  = lane & 3;
    const int b    = blockIdx.y;
    const int n0   = blockIdx.x * 64;

    const __half* Qg = g_theta + ((size_t)b * N_ + n0) * 64;
    const __half* Kg = g_phi   + (size_t)b * M_ * 64;
    const __half* Vg = g_v     + (size_t)b * CI * M_;

    // ---- stage Q ----
    for (int i = tid; i < 512; i += 256) {
        const int r = i >> 3, c = i & 7;
        *reinterpret_cast<uint4*>(smem + SM_Q + r * KROW + c * 16) =
            *reinterpret_cast<const uint4*>(Qg + (size_t)r * 64 + c * 8);
    }

    // ---- per-thread cp.async chunk coordinates (hoisted) ----
    const int kc = tid & 7;
    const int vc = tid & 15;
    auto issue_tile = [&](int t, int buf) {
        const __half* kb = Kg + (size_t)t * TKV * 64;
        const __half* vb = Vg + (size_t)t * TKV;
        const uint32_t kd = sbase + SM_K + buf * 24576;
        const uint32_t vd = sbase + SM_V + buf * 10240;
#pragma unroll
        for (int i = 0; i < 4; i++) {
            const int r = (tid + i * 256) >> 3;
            CP16(kd + r * KROW + kc * 16, kb + (size_t)r * 64 + kc * 8);
        }
#pragma unroll
        for (int i = 0; i < 2; i++) {
            const int ci = (tid + i * 256) >> 4;
            CP16(vd + ci * VROW + vc * 16, vb + (size_t)ci * M_ + vc * 8);
        }
    };

    issue_tile(0, 0);
    asm volatile("cp.async.commit_group;" ::: "memory");
    __syncthreads();   // Q stores visible

    // ---- Q fragments (permuted layout -> LDS.128 quads) ----
    uint32_t qh[2][4], ql[2][4];
    {
        const char* q1 = smem + SM_Q + (16 * wq + g) * KROW + 16 * tig;
        const char* q2 = smem + SM_Q + (16 * wq + g + 8) * KROW + 16 * tig;
        const uint4 hA = *reinterpret_cast<const uint4*>(q1);
        const uint4 hB = *reinterpret_cast<const uint4*>(q2);
        const uint4 lA4 = *reinterpret_cast<const uint4*>(q1 + 64);
        const uint4 lB4 = *reinterpret_cast<const uint4*>(q2 + 64);
        qh[0][0] = hA.x; qh[0][1] = hB.x; qh[0][2] = hA.y; qh[0][3] = hB.y;
        qh[1][0] = hA.z; qh[1][1] = hB.z; qh[1][2] = hA.w; qh[1][3] = hB.w;
        ql[0][0] = lA4.x; ql[0][1] = lB4.x; ql[0][2] = lA4.y; ql[0][3] = lB4.y;
        ql[1][0] = lA4.z; ql[1][1] = lB4.z; ql[1][2] = lA4.w; ql[1][3] = lB4.w;
    }

    // o[0..3]: ci 0..31; o[4]: virtual ones-channel (col 0 = row-sum l)
    float o[5][4];
#pragma unroll
    for (int i = 0; i < 5; i++)
#pragma unroll
        for (int k = 0; k < 4; k++) o[i][k] = 0.f;
    float mA = -1e30f, mB = -1e30f;   // invariant: integer (or -1e30 initially)

    // constant B-fragment for the ones channel: n = lane/4 == 0 -> (1,1) else 0
    const uint32_t ones = (g == 0) ? 0x3C003C00u : 0u;

    for (int u = 0; u < NT; u++) {
        asm volatile("cp.async.wait_group 0;" ::: "memory");
        __syncthreads();   // tile u ready; all warps done with buffer (u+1)&1

        if (u + 1 < NT) {
            issue_tile(u + 1, (u + 1) & 1);
            asm volatile("cp.async.commit_group;" ::: "memory");
        }

        const int buf = u & 1;
        const char* Kb = smem + SM_K + buf * 24576 + (64 * ch + g) * KROW + 16 * tig;
        const char* Vh = smem + SM_V + buf * 10240 + g * VROW + ch * 128 + 16 * tig;

        // ---- S = Q K^T : 8 n-tiles x (2 LDS.128 + 6 HMMA) ----
        float c[8][4];
#pragma unroll
        for (int nt = 0; nt < 8; nt++) {
            c[nt][0] = c[nt][1] = c[nt][2] = c[nt][3] = 0.f;
            const char* kr = Kb + nt * 8 * KROW;
            const uint4 bh = *reinterpret_cast<const uint4*>(kr);
            const uint4 bl = *reinterpret_cast<const uint4*>(kr + 64);
            MMA4(c[nt], qh[0][0], qh[0][1], qh[0][2], qh[0][3], bh.x, bh.y);
            MMA4(c[nt], qh[0][0], qh[0][1], qh[0][2], qh[0][3], bl.x, bl.y);
            MMA4(c[nt], ql[0][0], ql[0][1], ql[0][2], ql[0][3], bh.x, bh.y);
            MMA4(c[nt], qh[1][0], qh[1][1], qh[1][2], qh[1][3], bh.z, bh.w);
            MMA4(c[nt], qh[1][0], qh[1][1], qh[1][2], qh[1][3], bl.z, bl.w);
            MMA4(c[nt], ql[1][0], ql[1][1], ql[1][2], ql[1][3], bh.z, bh.w);
        }

        // ---- running max (quantized to INTEGER) + O rescale ----
        float mxA = fmaxf(c[0][0], c[0][1]);
        float mxB = fmaxf(c[0][2], c[0][3]);
#pragma unroll
        for (int nt = 1; nt < 8; nt++) {
            mxA = fmaxf(mxA, fmaxf(c[nt][0], c[nt][1]));
            mxB = fmaxf(mxB, fmaxf(c[nt][2], c[nt][3]));
        }
        mxA = fmaxf(mxA, __shfl_xor_sync(0xffffffffu, mxA, 1));
        mxA = fmaxf(mxA, __shfl_xor_sync(0xffffffffu, mxA, 2));
        mxB = fmaxf(mxB, __shfl_xor_sync(0xffffffffu, mxB, 1));
        mxB = fmaxf(mxB, __shfl_xor_sync(0xffffffffu, mxB, 2));
        // quantize tile max to nearest integer so K1 = 12582912 - m is EXACT
        const float mxAq = (mxA + 12582912.0f) - 12582912.0f;
        const float mxBq = (mxB + 12582912.0f) - 12582912.0f;
        const float mAn = fmaxf(mA, mxAq);
        const float mBn = fmaxf(mB, mxBq);
        const float sA  = fexp2(fmaxf(mA - mAn, -126.f));   // integer args -> exact
        const float sB  = fexp2(fmaxf(mB - mBn, -126.f));
        mA = mAn; mB = mBn;
#pragma unroll
        for (int nt = 0; nt < 5; nt++) {
            o[nt][0] *= sA; o[nt][1] *= sA;
            o[nt][2] *= sB; o[nt][3] *= sB;
        }

        // ---- exp2(s - m): integer max folded into range-reduction constant ----
        const float K1A = 12582912.0f - mA;
        const float K1B = 12582912.0f - mB;
#pragma unroll
        for (int nt = 0; nt < 8; nt++) {
            c[nt][0] = fexp2f(c[nt][0], K1A);
            c[nt][1] = fexp2f(c[nt][1], K1A);
            c[nt][2] = fexp2f(c[nt][2], K1B);
            c[nt][3] = fexp2f(c[nt][3], K1B);
        }

        // ---- O += P V (fp16 single product); l-column via constant fragment ----
#pragma unroll
        for (int p = 0; p < 2; p++) {
            uint32_t pa0[4], pa1[4];
            pa0[0] = pkh2(c[4*p][0],   c[4*p][1]);
            pa0[1] = pkh2(c[4*p][2],   c[4*p][3]);
            pa0[2] = pkh2(c[4*p+1][0], c[4*p+1][1]);
            pa0[3] = pkh2(c[4*p+1][2], c[4*p+1][3]);
            pa1[0] = pkh2(c[4*p+2][0], c[4*p+2][1]);
            pa1[1] = pkh2(c[4*p+2][2], c[4*p+2][3]);
            pa1[2] = pkh2(c[4*p+3][0], c[4*p+3][1]);
            pa1[3] = pkh2(c[4*p+3][2], c[4*p+3][3]);
#pragma unroll
            for (int nt = 0; nt < 4; nt++) {
                const uint4 vh4 = *reinterpret_cast<const uint4*>(Vh + nt * 8 * VROW + p * 64);
                MMA4(o[nt], pa0[0], pa0[1], pa0[2], pa0[3], vh4.x, vh4.y);
                MMA4(o[nt], pa1[0], pa1[1], pa1[2], pa1[3], vh4.z, vh4.w);
            }
            MMA4(o[4], pa0[0], pa0[1], pa0[2], pa0[3], ones, ones);
            MMA4(o[4], pa1[0], pa1[1], pa1[2], pa1[3], ones, ones);
        }
    }

    // ---- extract l (col 0 of ones-channel lives in tig==0 lanes) ----
    const int qroot = lane & ~3;
    const float lA = __shfl_sync(0xffffffffu, o[4][0], qroot);
    const float lB = __shfl_sync(0xffffffffu, o[4][2], qroot);

    // ---- combine column halves (max-aware) ----
    float* ost = reinterpret_cast<float*>(smem + SM_V);         // [64][34]
    float* ls  = reinterpret_cast<float*>(smem + SM_LS);        // [64]
    float* ms  = reinterpret_cast<float*>(smem + SM_MS);        // [64]
    float* ys  = reinterpret_cast<float*>(smem + SM_K);         // [64][33]
    float* wo  = reinterpret_cast<float*>(smem + SM_K + 16384); // [64][32]

    const int rA = 16 * wq + g, rB = rA + 8;
    if (ch == 1) {
#pragma unroll
        for (int nt = 0; nt < 4; nt++) {
            const int ci = 8 * nt + 2 * tig;
            ost[rA * 34 + ci]     = o[nt][0];
            ost[rA * 34 + ci + 1] = o[nt][1];
            ost[rB * 34 + ci]     = o[nt][2];
            ost[rB * 34 + ci + 1] = o[nt][3];
        }
        if (tig == 0) { ls[rA] = lA; ls[rB] = lB; ms[rA] = mA; ms[rB] = mB; }
    }
    for (int i = tid; i < C_ * CI; i += 256) wo[i] = w_out[i];
    __syncthreads();

    if (ch == 0) {
        const float m1A = ms[rA], m1B = ms[rB];
        const float MtA = fmaxf(mA, m1A), MtB = fmaxf(mB, m1B);
        const float a0 = fexp2(fmaxf(mA - MtA, -126.f));
        const float a1 = fexp2(fmaxf(m1A - MtA, -126.f));
        const float b0 = fexp2(fmaxf(mB - MtB, -126.f));
        const float b1 = fexp2(fmaxf(m1B - MtB, -126.f));
        const float iA = 1.f / (lA * a0 + ls[rA] * a1);
        const float iB = 1.f / (lB * b0 + ls[rB] * b1);
        const float fA0 = a0 * iA, fA1 = a1 * iA;
        const float fB0 = b0 * iB, fB1 = b1 * iB;
#pragma unroll
        for (int nt = 0; nt < 4; nt++) {
            const int ci = 8 * nt + 2 * tig;
            ys[rA * 33 + ci]     = o[nt][0] * fA0 + ost[rA * 34 + ci]     * fA1;
            ys[rA * 33 + ci + 1] = o[nt][1] * fA0 + ost[rA * 34 + ci + 1] * fA1;
            ys[rB * 33 + ci]     = o[nt][2] * fB0 + ost[rB * 34 + ci]     * fB1;
            ys[rB * 33 + ci + 1] = o[nt][3] * fB0 + ost[rB * 34 + ci + 1] * fB1;
        }
    }
    __syncthreads();

    // ---- out-proj + residual: thread = (row r, 16 channels) ----
    {
        const int r  = tid & 63;
        const int cq = tid >> 6;
        float y[CI];
#pragma unroll
        for (int i = 0; i < CI; i++) y[i] = ys[r * 33 + i];
        const float* xb = x   + (size_t)b * C_ * N_;
        float*       ob = out + (size_t)b * C_ * N_;
#pragma unroll 4
        for (int c = cq * 16; c < cq * 16 + 16; c++) {
            float acc = __ldg(&b_out[c]);
            const float* w = &wo[c * CI];
#pragma unroll
            for (int i = 0; i < CI; i++) acc += y[i] * w[i];
            const size_t gi = (size_t)c * N_ + n0 + r;
            ob[gi] = acc + xb[gi];
        }
    }
}

// =====================================================================
extern "C" void kernel_launch(void* const* d_in, const int* in_sizes, int n_in,
                              void* d_out, int out_size)
{
    const float* x  = (const float*)d_in[0];
    const float* wt = (const float*)d_in[1];
    const float* bt = (const float*)d_in[2];
    const float* wp = (const float*)d_in[3];
    const float* bp = (const float*)d_in[4];
    const float* wg = (const float*)d_in[5];
    const float* bg = (const float*)d_in[6];
    const float* wo = (const float*)d_in[7];
    const float* bo = (const float*)d_in[8];
    float* out = (float*)d_out;

    static bool attr_set = false;
    if (!attr_set) {
        cudaFuncSetAttribute(attn_kernel, cudaFuncAttributeMaxDynamicSharedMemorySize, SMEM_TOTAL);
        attr_set = true;
    }

    proj_kernel<<<dim3(N_ / 64, B_), 256>>>(x, wt, bt, wp, bp, wg, bg);
    attn_kernel<<<dim3(N_ / 64, B_), 256, SMEM_TOTAL>>>(x, wo, bo, out);
}